// round 2
// baseline (speedup 1.0000x reference)
#include <cuda_runtime.h>
#include <cstddef>

// Problem constants
// B=8, T=1024, D=1024, N=256, L=768, H=16, hd=64, TE=2048

// ---------------- scratch (device globals; no runtime allocation) ----------------
__device__ float g_xn [8192u*1024u];   // LN(x)        (B*T, D)
__device__ float g_xfn[2048u*768u];    // LN(xf)       (B*N, L)
__device__ float g_q  [8192u*1024u];   // q            (B*T, D)
__device__ float g_k  [2048u*1024u];   // k            (B*N, D)
__device__ float g_v  [2048u*1024u];   // v            (B*N, D)
__device__ float g_y  [8192u*1024u];   // attn output  (B*T, D)
__device__ float g_embo[8u*2048u];     // silu(emb)@Wemb+bemb  (B, 2D)
__device__ float g_hn [8192u*1024u];   // silu(modulated LN(y)) (B*T, D)

// ---------------- LayerNorm (one block per row) ----------------
__global__ void ln_kernel(const float* __restrict__ X, const float* __restrict__ gam,
                          const float* __restrict__ bet, float* __restrict__ O, int Wd) {
    int row = blockIdx.x;
    const float* xr = X + (size_t)row * Wd;
    float* orow = O + (size_t)row * Wd;
    float sum = 0.f, sq = 0.f;
    for (int i = threadIdx.x; i < Wd; i += blockDim.x) {
        float v = xr[i];
        sum += v; sq += v * v;
    }
    __shared__ float s1[8], s2[8];
    #pragma unroll
    for (int o = 16; o; o >>= 1) {
        sum += __shfl_xor_sync(0xffffffffu, sum, o);
        sq  += __shfl_xor_sync(0xffffffffu, sq,  o);
    }
    int w = threadIdx.x >> 5, l = threadIdx.x & 31;
    if (l == 0) { s1[w] = sum; s2[w] = sq; }
    __syncthreads();
    __shared__ float mean_s, inv_s;
    if (threadIdx.x == 0) {
        float ts = 0.f, tq = 0.f;
        int nw = blockDim.x >> 5;
        for (int i = 0; i < nw; i++) { ts += s1[i]; tq += s2[i]; }
        float mean = ts / Wd;
        float var = tq / Wd - mean * mean;
        mean_s = mean;
        inv_s = rsqrtf(var + 1e-5f);
    }
    __syncthreads();
    float mean = mean_s, inv = inv_s;
    for (int i = threadIdx.x; i < Wd; i += blockDim.x)
        orow[i] = (xr[i] - mean) * inv * gam[i] + bet[i];
}

// ---------------- fp32 tiled GEMM: C[M,N] = A[M,K] @ W[K,N] + bias (+ R) ----------------
// 128x128 block tile, BK=8, 256 threads, 8x8 per-thread register tile.
template<bool RES>
__global__ void __launch_bounds__(256) sgemm128(const float* __restrict__ A,
                                                const float* __restrict__ W,
                                                const float* __restrict__ bias,
                                                const float* __restrict__ R,
                                                float* __restrict__ C,
                                                int M, int Nn, int K) {
    __shared__ float As[8][128];
    __shared__ float Bs[8][128];
    int bm = blockIdx.y * 128, bn = blockIdx.x * 128;
    int tid = threadIdx.x;
    int tx = tid & 15, ty = tid >> 4;
    int ar = tid >> 1, ac = (tid & 1) * 4;
    int br = tid >> 5, bc = (tid & 31) * 4;
    const float* Ap = A + (size_t)(bm + ar) * K + ac;
    const float* Wp = W + (size_t)br * Nn + bn + bc;
    float acc[8][8] = {};
    for (int k0 = 0; k0 < K; k0 += 8) {
        float4 av = *(const float4*)(Ap + k0);
        float4 bv = *(const float4*)(Wp + (size_t)k0 * Nn);
        As[ac + 0][ar] = av.x; As[ac + 1][ar] = av.y;
        As[ac + 2][ar] = av.z; As[ac + 3][ar] = av.w;
        *(float4*)&Bs[br][bc] = bv;
        __syncthreads();
        #pragma unroll
        for (int kk = 0; kk < 8; kk++) {
            float ra[8], rb[8];
            *(float4*)&ra[0] = *(const float4*)&As[kk][ty * 8];
            *(float4*)&ra[4] = *(const float4*)&As[kk][ty * 8 + 4];
            *(float4*)&rb[0] = *(const float4*)&Bs[kk][tx * 8];
            *(float4*)&rb[4] = *(const float4*)&Bs[kk][tx * 8 + 4];
            #pragma unroll
            for (int i = 0; i < 8; i++)
                #pragma unroll
                for (int j = 0; j < 8; j++)
                    acc[i][j] += ra[i] * rb[j];
        }
        __syncthreads();
    }
    #pragma unroll
    for (int i = 0; i < 8; i++) {
        size_t row = (size_t)(bm + ty * 8 + i);
        size_t base = row * Nn + bn + tx * 8;
        #pragma unroll
        for (int j0 = 0; j0 < 8; j0 += 4) {
            float4 r;
            r.x = acc[i][j0 + 0] + bias[bn + tx * 8 + j0 + 0];
            r.y = acc[i][j0 + 1] + bias[bn + tx * 8 + j0 + 1];
            r.z = acc[i][j0 + 2] + bias[bn + tx * 8 + j0 + 2];
            r.w = acc[i][j0 + 3] + bias[bn + tx * 8 + j0 + 3];
            if (RES) {
                float4 rr = *(const float4*)&R[base + j0];
                r.x += rr.x; r.y += rr.y; r.z += rr.z; r.w += rr.w;
            }
            *(float4*)&C[base + j0] = r;
        }
    }
}

// ---------------- fused attention per (b, h, 16-row q tile) ----------------
// grid: (T/16=64, H=16, B=8), 128 threads. K/V chunks of 64 rows staged in SMEM,
// full scores (16x256) in SMEM, two-pass softmax.
__global__ void __launch_bounds__(128) attn_kernel() {
    __shared__ float qs[16][65];
    __shared__ float S [16][257];
    __shared__ float kv[64][65];
    int t0 = blockIdx.x * 16, h = blockIdx.y, b = blockIdx.z;
    int tid = threadIdx.x;

    for (int i = tid; i < 16 * 64; i += 128) {
        int t = i >> 6, d = i & 63;
        qs[t][d] = g_q[(size_t)(b * 1024 + t0 + t) * 1024 + h * 64 + d];
    }
    __syncthreads();

    int tr = tid & 7;     // t = tr*2 + i (i<2)
    int nc = tid >> 3;    // n = nc*4 + j (j<4)   [score phase]
    // -------- scores --------
    for (int c = 0; c < 4; c++) {
        for (int i = tid; i < 64 * 64; i += 128) {
            int n = i >> 6, d = i & 63;
            kv[n][d] = g_k[(size_t)(b * 256 + c * 64 + n) * 1024 + h * 64 + d];
        }
        __syncthreads();
        float a[2][4] = {};
        #pragma unroll 4
        for (int d = 0; d < 64; d++) {
            float q0 = qs[tr * 2 + 0][d];
            float q1 = qs[tr * 2 + 1][d];
            float k0 = kv[nc * 4 + 0][d];
            float k1 = kv[nc * 4 + 1][d];
            float k2 = kv[nc * 4 + 2][d];
            float k3 = kv[nc * 4 + 3][d];
            a[0][0] += q0 * k0; a[0][1] += q0 * k1; a[0][2] += q0 * k2; a[0][3] += q0 * k3;
            a[1][0] += q1 * k0; a[1][1] += q1 * k1; a[1][2] += q1 * k2; a[1][3] += q1 * k3;
        }
        #pragma unroll
        for (int i = 0; i < 2; i++)
            #pragma unroll
            for (int j = 0; j < 4; j++)
                S[tr * 2 + i][c * 64 + nc * 4 + j] = a[i][j] * 0.125f;
        __syncthreads();
    }
    // -------- softmax over n (row r handled by 8 contiguous threads) --------
    {
        int r = tid >> 3, sub = tid & 7;
        float m = -1e30f;
        for (int n = sub; n < 256; n += 8) m = fmaxf(m, S[r][n]);
        #pragma unroll
        for (int o = 4; o; o >>= 1) m = fmaxf(m, __shfl_xor_sync(0xffffffffu, m, o));
        float s = 0.f;
        for (int n = sub; n < 256; n += 8) {
            float e = __expf(S[r][n] - m);
            S[r][n] = e;
            s += e;
        }
        #pragma unroll
        for (int o = 4; o; o >>= 1) s += __shfl_xor_sync(0xffffffffu, s, o);
        float invs = 1.f / s;
        for (int n = sub; n < 256; n += 8) S[r][n] *= invs;
    }
    __syncthreads();
    // -------- y = w @ v --------
    int dc = tid >> 3;    // d = dc*4 + j
    float acc[2][4] = {};
    for (int c = 0; c < 4; c++) {
        for (int i = tid; i < 64 * 64; i += 128) {
            int n = i >> 6, d = i & 63;
            kv[n][d] = g_v[(size_t)(b * 256 + c * 64 + n) * 1024 + h * 64 + d];
        }
        __syncthreads();
        #pragma unroll 4
        for (int n = 0; n < 64; n++) {
            float w0 = S[tr * 2 + 0][c * 64 + n];
            float w1 = S[tr * 2 + 1][c * 64 + n];
            float v0 = kv[n][dc * 4 + 0];
            float v1 = kv[n][dc * 4 + 1];
            float v2 = kv[n][dc * 4 + 2];
            float v3 = kv[n][dc * 4 + 3];
            acc[0][0] += w0 * v0; acc[0][1] += w0 * v1; acc[0][2] += w0 * v2; acc[0][3] += w0 * v3;
            acc[1][0] += w1 * v0; acc[1][1] += w1 * v1; acc[1][2] += w1 * v2; acc[1][3] += w1 * v3;
        }
        __syncthreads();
    }
    #pragma unroll
    for (int i = 0; i < 2; i++) {
        float4 r = make_float4(acc[i][0], acc[i][1], acc[i][2], acc[i][3]);
        *(float4*)&g_y[(size_t)(b * 1024 + t0 + tr * 2 + i) * 1024 + h * 64 + dc * 4] = r;
    }
}

// ---------------- silu(emb) @ Wemb + bemb -> g_embo  (M=8 GEMV-like) ----------------
__global__ void __launch_bounds__(256) emb_gemv(const float* __restrict__ emb,
                                                const float* __restrict__ Wemb,
                                                const float* __restrict__ bemb) {
    int j = blockIdx.x * 256 + threadIdx.x;
    __shared__ float se[8][256];
    float acc[8] = {};
    for (int tt0 = 0; tt0 < 2048; tt0 += 256) {
        for (int i = threadIdx.x; i < 2048; i += 256) {
            int bb = i >> 8, t = i & 255;
            float e = emb[bb * 2048 + tt0 + t];
            se[bb][t] = e / (1.f + __expf(-e));
        }
        __syncthreads();
        #pragma unroll 4
        for (int t = 0; t < 256; t++) {
            float w = Wemb[(size_t)(tt0 + t) * 2048 + j];
            #pragma unroll
            for (int bb = 0; bb < 8; bb++) acc[bb] += se[bb][t] * w;
        }
        __syncthreads();
    }
    #pragma unroll
    for (int bb = 0; bb < 8; bb++)
        g_embo[bb * 2048 + j] = acc[bb] + bemb[j];
}

// ---------------- LN(y)*(1+scale)+shift -> silu -> g_hn ----------------
__global__ void modulate_kernel(const float* __restrict__ gam, const float* __restrict__ bet) {
    int row = blockIdx.x;
    int b = row >> 10;
    const float* yr = g_y + (size_t)row * 1024;
    float sum = 0.f, sq = 0.f;
    for (int i = threadIdx.x; i < 1024; i += blockDim.x) {
        float v = yr[i];
        sum += v; sq += v * v;
    }
    __shared__ float s1[8], s2[8];
    #pragma unroll
    for (int o = 16; o; o >>= 1) {
        sum += __shfl_xor_sync(0xffffffffu, sum, o);
        sq  += __shfl_xor_sync(0xffffffffu, sq,  o);
    }
    int w = threadIdx.x >> 5, l = threadIdx.x & 31;
    if (l == 0) { s1[w] = sum; s2[w] = sq; }
    __syncthreads();
    __shared__ float mean_s, inv_s;
    if (threadIdx.x == 0) {
        float ts = 0.f, tq = 0.f;
        for (int i = 0; i < 8; i++) { ts += s1[i]; tq += s2[i]; }
        float mean = ts * (1.f / 1024.f);
        float var = tq * (1.f / 1024.f) - mean * mean;
        mean_s = mean;
        inv_s = rsqrtf(var + 1e-5f);
    }
    __syncthreads();
    float mean = mean_s, inv = inv_s;
    for (int i = threadIdx.x; i < 1024; i += blockDim.x) {
        float nv = (yr[i] - mean) * inv * gam[i] + bet[i];
        float sc = g_embo[b * 2048 + i];
        float sh = g_embo[b * 2048 + 1024 + i];
        float hv = nv * (1.f + sc) + sh;
        g_hn[(size_t)row * 1024 + i] = hv / (1.f + __expf(-hv));
    }
}

// ---------------- launch ----------------
extern "C" void kernel_launch(void* const* d_in, const int* in_sizes, int n_in,
                              void* d_out, int out_size) {
    const float* x     = (const float*)d_in[0];
    const float* xf    = (const float*)d_in[1];
    const float* emb   = (const float*)d_in[2];
    const float* ln_g  = (const float*)d_in[3];
    const float* ln_b  = (const float*)d_in[4];
    const float* cln_g = (const float*)d_in[5];
    const float* cln_b = (const float*)d_in[6];
    const float* Wq    = (const float*)d_in[7];
    const float* bq    = (const float*)d_in[8];
    const float* Wk    = (const float*)d_in[9];
    const float* bk    = (const float*)d_in[10];
    const float* Wv    = (const float*)d_in[11];
    const float* bv    = (const float*)d_in[12];
    const float* sln_g = (const float*)d_in[13];
    const float* sln_b = (const float*)d_in[14];
    const float* Wemb  = (const float*)d_in[15];
    const float* bemb  = (const float*)d_in[16];
    const float* Wout  = (const float*)d_in[17];
    const float* bout  = (const float*)d_in[18];
    float* out = (float*)d_out;

    float *xn, *xfn, *q, *k, *v, *hn;
    cudaGetSymbolAddress((void**)&xn,  g_xn);
    cudaGetSymbolAddress((void**)&xfn, g_xfn);
    cudaGetSymbolAddress((void**)&q,   g_q);
    cudaGetSymbolAddress((void**)&k,   g_k);
    cudaGetSymbolAddress((void**)&v,   g_v);
    cudaGetSymbolAddress((void**)&hn,  g_hn);

    // 1) LayerNorms
    ln_kernel<<<8192, 256>>>(x,  ln_g,  ln_b,  xn,  1024);
    ln_kernel<<<2048, 256>>>(xf, cln_g, cln_b, xfn, 768);

    // 2) Projections
    sgemm128<false><<<dim3(8, 64), 256>>>(xn,  Wq, bq, nullptr, q, 8192, 1024, 1024);
    sgemm128<false><<<dim3(8, 16), 256>>>(xfn, Wk, bk, nullptr, k, 2048, 1024, 768);
    sgemm128<false><<<dim3(8, 16), 256>>>(xfn, Wv, bv, nullptr, v, 2048, 1024, 768);

    // 3) Attention
    attn_kernel<<<dim3(64, 16, 8), 128>>>();

    // 4) Stylization: emb path + modulate + silu
    emb_gemv<<<8, 256>>>(emb, Wemb, bemb);
    modulate_kernel<<<8192, 256>>>(sln_g, sln_b);

    // 5) Output projection + residual
    sgemm128<true><<<dim3(8, 64), 256>>>(hn, Wout, bout, x, out, 8192, 1024, 1024);
}

// round 4
// speedup vs baseline: 1.5809x; 1.5809x over previous
#include <cuda_runtime.h>
#include <cuda_bf16.h>
#include <cstdint>
#include <cstddef>

// Problem constants: B=8, T=1024, D=1024, N=256, L=768, H=16, hd=64, TE=2048

// ================= helpers =================
__device__ __forceinline__ uint32_t smem_u32(const void* p) {
    uint32_t a;
    asm("{ .reg .u64 t; cvta.to.shared.u64 t, %1; cvt.u32.u64 %0, t; }" : "=r"(a) : "l"(p));
    return a;
}
#define CP_ASYNC16(smem, gptr) \
    asm volatile("cp.async.cg.shared.global [%0], [%1], 16;" :: "r"(smem), "l"(gptr))
#define CP_ASYNC_COMMIT() asm volatile("cp.async.commit_group;" ::: "memory")

__device__ __forceinline__ void ldsm_x4(uint32_t& r0, uint32_t& r1, uint32_t& r2, uint32_t& r3,
                                        uint32_t addr) {
    asm volatile("ldmatrix.sync.aligned.m8n8.x4.shared.b16 {%0,%1,%2,%3}, [%4];"
                 : "=r"(r0), "=r"(r1), "=r"(r2), "=r"(r3) : "r"(addr));
}
__device__ __forceinline__ void mma16816(float* d, const uint32_t* a, const uint32_t* b) {
    asm volatile("mma.sync.aligned.m16n8k16.row.col.f32.bf16.bf16.f32 "
                 "{%0,%1,%2,%3}, {%4,%5,%6,%7}, {%8,%9}, {%0,%1,%2,%3};"
                 : "+f"(d[0]), "+f"(d[1]), "+f"(d[2]), "+f"(d[3])
                 : "r"(a[0]), "r"(a[1]), "r"(a[2]), "r"(a[3]), "r"(b[0]), "r"(b[1]));
}

// ================= scratch (device globals) =================
__device__ float g_q  [8192u*1024u];
__device__ float g_k  [2048u*1024u];
__device__ float g_v  [2048u*1024u];
__device__ float g_y  [8192u*1024u];
__device__ float g_embo[8u*2048u];
__device__ __nv_bfloat16 g_xnh[8192u*1024u], g_xnl[8192u*1024u];   // LN(x) hi/lo
__device__ __nv_bfloat16 g_xfh[2048u*768u],  g_xfl[2048u*768u];    // LN(xf) hi/lo
__device__ __nv_bfloat16 g_hnh[8192u*1024u], g_hnl[8192u*1024u];   // silu(mod) hi/lo
__device__ __nv_bfloat16 g_wqh[1024u*1024u], g_wql[1024u*1024u];   // Wq^T hi/lo [N,K]
__device__ __nv_bfloat16 g_wkh[1024u*768u],  g_wkl[1024u*768u];
__device__ __nv_bfloat16 g_wvh[1024u*768u],  g_wvl[1024u*768u];
__device__ __nv_bfloat16 g_woh[1024u*1024u], g_wol[1024u*1024u];

// ================= LayerNorm -> bf16 hi/lo =================
__global__ void ln_split_kernel(const float* __restrict__ X, const float* __restrict__ gam,
                                const float* __restrict__ bet, __nv_bfloat16* __restrict__ Ohi,
                                __nv_bfloat16* __restrict__ Olo, int Wd) {
    int row = blockIdx.x;
    const float* xr = X + (size_t)row * Wd;
    float sum = 0.f, sq = 0.f;
    for (int i = threadIdx.x; i < Wd; i += blockDim.x) {
        float v = xr[i];
        sum += v; sq += v * v;
    }
    __shared__ float s1[8], s2[8];
    #pragma unroll
    for (int o = 16; o; o >>= 1) {
        sum += __shfl_xor_sync(0xffffffffu, sum, o);
        sq  += __shfl_xor_sync(0xffffffffu, sq,  o);
    }
    int w = threadIdx.x >> 5, l = threadIdx.x & 31;
    if (l == 0) { s1[w] = sum; s2[w] = sq; }
    __syncthreads();
    __shared__ float mean_s, inv_s;
    if (threadIdx.x == 0) {
        float ts = 0.f, tq = 0.f;
        int nw = blockDim.x >> 5;
        for (int i = 0; i < nw; i++) { ts += s1[i]; tq += s2[i]; }
        float mean = ts / Wd;
        float var = tq / Wd - mean * mean;
        mean_s = mean;
        inv_s = rsqrtf(var + 1e-5f);
    }
    __syncthreads();
    float mean = mean_s, inv = inv_s;
    for (int i = threadIdx.x; i < Wd; i += blockDim.x) {
        float v = (xr[i] - mean) * inv * gam[i] + bet[i];
        __nv_bfloat16 hi = __float2bfloat16(v);
        Ohi[(size_t)row * Wd + i] = hi;
        Olo[(size_t)row * Wd + i] = __float2bfloat16(v - __bfloat162float(hi));
    }
}

// ================= weight transpose + split: W[K,N] fp32 -> T[N,K] bf16 hi/lo =================
__global__ void wsplit_kernel(const float* __restrict__ W, __nv_bfloat16* __restrict__ Thi,
                              __nv_bfloat16* __restrict__ Tlo, int K, int Nn) {
    __shared__ float t[32][33];
    int k0 = blockIdx.x * 32, n0 = blockIdx.y * 32;
    int tx = threadIdx.x, ty = threadIdx.y;  // (32, 8)
    #pragma unroll
    for (int r = ty; r < 32; r += 8)
        t[r][tx] = W[(size_t)(k0 + r) * Nn + n0 + tx];
    __syncthreads();
    #pragma unroll
    for (int r = ty; r < 32; r += 8) {
        float v = t[tx][r];  // W[k0+tx][n0+r]
        __nv_bfloat16 hi = __float2bfloat16(v);
        size_t o = (size_t)(n0 + r) * K + k0 + tx;
        Thi[o] = hi;
        Tlo[o] = __float2bfloat16(v - __bfloat162float(hi));
    }
}

// ================= mma.sync split-bf16 GEMM =================
// C[M,Nn] = (Ahi+Alo)[M,K] @ (Bhi+Blo)[Nn,K]^T + bias (+ R), fp32 out.
// 128x128 tile, 256 threads (2x4 warps, 64x32/warp), BK=32, cp.async double buffer.
// SMEM tile row stride = 80 bytes (32 bf16 + 8 pad) -> conflict-free ldmatrix.
static constexpr uint32_t TSTRIDE = 80;
static constexpr uint32_t TILE_B  = 128 * TSTRIDE;          // 10240
static constexpr uint32_t STAGE_B = 4 * TILE_B;             // 40960 (Ahi,Alo,Bhi,Blo)

template<bool RES>
__global__ void __launch_bounds__(256) mma_gemm(
    const __nv_bfloat16* __restrict__ Ahi, const __nv_bfloat16* __restrict__ Alo,
    const __nv_bfloat16* __restrict__ Bhi, const __nv_bfloat16* __restrict__ Blo,
    const float* __restrict__ bias, const float* __restrict__ R,
    float* __restrict__ C, int M, int Nn, int K) {
    extern __shared__ char smem[];
    uint32_t sbase = smem_u32(smem);

    int tid = threadIdx.x, wid = tid >> 5, lane = tid & 31;
    int wm = wid >> 2, wn = wid & 3;          // warp tile origin: (wm*64, wn*32)
    int bm = blockIdx.y * 128, bn = blockIdx.x * 128;

    const __nv_bfloat16* gsrc[4] = {
        Ahi + (size_t)bm * K, Alo + (size_t)bm * K,
        Bhi + (size_t)bn * K, Blo + (size_t)bn * K };

    float acc[4][4][4] = {};   // [mt][nt][reg]

    const int NC = K >> 5;
    // ---- loader ----
    auto load_stage = [&](int c) {
        uint32_t sb = sbase + (uint32_t)(c & 1) * STAGE_B;
        int kc = c * 32;
        #pragma unroll
        for (int t = 0; t < 4; t++) {
            const __nv_bfloat16* g = gsrc[t] + kc;
            uint32_t tb = sb + t * TILE_B;
            #pragma unroll
            for (int i = tid; i < 512; i += 256) {
                int r = i >> 2, q = i & 3;
                CP_ASYNC16(tb + r * TSTRIDE + q * 16, g + (size_t)r * K + q * 8);
            }
        }
    };

    load_stage(0);
    CP_ASYNC_COMMIT();

    // lane addressing (constant over loop)
    uint32_t aRow = (uint32_t)(wm * 64) + ((lane >> 3) & 1) * 8 + (lane & 7);
    uint32_t aCol = ((lane >> 4) * 8) * 2;                 // bytes
    uint32_t bRow = (uint32_t)(wn * 32) + ((lane >> 4) * 8) + (lane & 7);
    uint32_t bCol = (((lane >> 3) & 1) * 8) * 2;           // bytes

    for (int c = 0; c < NC; c++) {
        if (c + 1 < NC) { load_stage(c + 1); CP_ASYNC_COMMIT(); }
        if (c + 1 < NC) asm volatile("cp.async.wait_group 1;" ::: "memory");
        else            asm volatile("cp.async.wait_group 0;" ::: "memory");
        __syncthreads();

        uint32_t sb = sbase + (uint32_t)(c & 1) * STAGE_B;
        #pragma unroll
        for (int kk = 0; kk < 2; kk++) {
            uint32_t kOff = kk * 32;  // 16 bf16 = 32 bytes
            uint32_t ah[4][4], al[4][4], bh[4][2], bl[4][2];
            #pragma unroll
            for (int mt = 0; mt < 4; mt++) {
                uint32_t ad = sb + (aRow + mt * 16) * TSTRIDE + aCol + kOff;
                ldsm_x4(ah[mt][0], ah[mt][1], ah[mt][2], ah[mt][3], ad);
                ldsm_x4(al[mt][0], al[mt][1], al[mt][2], al[mt][3], ad + TILE_B);
            }
            #pragma unroll
            for (int np = 0; np < 2; np++) {
                uint32_t bd = sb + 2 * TILE_B + (bRow + np * 16) * TSTRIDE + bCol + kOff;
                ldsm_x4(bh[np*2][0], bh[np*2][1], bh[np*2+1][0], bh[np*2+1][1], bd);
                ldsm_x4(bl[np*2][0], bl[np*2][1], bl[np*2+1][0], bl[np*2+1][1], bd + TILE_B);
            }
            #pragma unroll
            for (int mt = 0; mt < 4; mt++)
                #pragma unroll
                for (int nt = 0; nt < 4; nt++) {
                    mma16816(acc[mt][nt], ah[mt], bh[nt]);
                    mma16816(acc[mt][nt], ah[mt], bl[nt]);
                    mma16816(acc[mt][nt], al[mt], bh[nt]);
                }
        }
        __syncthreads();
    }

    // ---- epilogue ----
    int g = lane >> 2, tg = lane & 3;
    #pragma unroll
    for (int mt = 0; mt < 4; mt++) {
        int r0 = bm + wm * 64 + mt * 16 + g;
        #pragma unroll
        for (int nt = 0; nt < 4; nt++) {
            int col = bn + wn * 32 + nt * 8 + tg * 2;
            float b0 = bias[col], b1 = bias[col + 1];
            size_t o0 = (size_t)r0 * Nn + col;
            size_t o1 = (size_t)(r0 + 8) * Nn + col;
            float2 v0 = make_float2(acc[mt][nt][0] + b0, acc[mt][nt][1] + b1);
            float2 v1 = make_float2(acc[mt][nt][2] + b0, acc[mt][nt][3] + b1);
            if (RES) {
                float2 r00 = *(const float2*)&R[o0];
                float2 r11 = *(const float2*)&R[o1];
                v0.x += r00.x; v0.y += r00.y;
                v1.x += r11.x; v1.y += r11.y;
            }
            *(float2*)&C[o0] = v0;
            *(float2*)&C[o1] = v1;
        }
    }
}

// ================= fused attention (SIMT fp32) =================
__global__ void __launch_bounds__(128) attn_kernel() {
    __shared__ float qs[16][65];
    __shared__ float S [16][257];
    __shared__ float kv[64][65];
    int t0 = blockIdx.x * 16, h = blockIdx.y, b = blockIdx.z;
    int tid = threadIdx.x;

    for (int i = tid; i < 16 * 64; i += 128) {
        int t = i >> 6, d = i & 63;
        qs[t][d] = g_q[(size_t)(b * 1024 + t0 + t) * 1024 + h * 64 + d];
    }
    __syncthreads();

    int tr = tid & 7;
    int nc = tid >> 3;
    for (int c = 0; c < 4; c++) {
        for (int i = tid; i < 64 * 64; i += 128) {
            int n = i >> 6, d = i & 63;
            kv[n][d] = g_k[(size_t)(b * 256 + c * 64 + n) * 1024 + h * 64 + d];
        }
        __syncthreads();
        float a[2][4] = {};
        #pragma unroll 4
        for (int d = 0; d < 64; d++) {
            float q0 = qs[tr * 2 + 0][d];
            float q1 = qs[tr * 2 + 1][d];
            float k0 = kv[nc * 4 + 0][d];
            float k1 = kv[nc * 4 + 1][d];
            float k2 = kv[nc * 4 + 2][d];
            float k3 = kv[nc * 4 + 3][d];
            a[0][0] += q0 * k0; a[0][1] += q0 * k1; a[0][2] += q0 * k2; a[0][3] += q0 * k3;
            a[1][0] += q1 * k0; a[1][1] += q1 * k1; a[1][2] += q1 * k2; a[1][3] += q1 * k3;
        }
        #pragma unroll
        for (int i = 0; i < 2; i++)
            #pragma unroll
            for (int j = 0; j < 4; j++)
                S[tr * 2 + i][c * 64 + nc * 4 + j] = a[i][j] * 0.125f;
        __syncthreads();
    }
    {
        int r = tid >> 3, sub = tid & 7;
        float m = -1e30f;
        for (int n = sub; n < 256; n += 8) m = fmaxf(m, S[r][n]);
        #pragma unroll
        for (int o = 4; o; o >>= 1) m = fmaxf(m, __shfl_xor_sync(0xffffffffu, m, o));
        float s = 0.f;
        for (int n = sub; n < 256; n += 8) {
            float e = __expf(S[r][n] - m);
            S[r][n] = e;
            s += e;
        }
        #pragma unroll
        for (int o = 4; o; o >>= 1) s += __shfl_xor_sync(0xffffffffu, s, o);
        float invs = 1.f / s;
        for (int n = sub; n < 256; n += 8) S[r][n] *= invs;
    }
    __syncthreads();
    int dc = tid >> 3;
    float acc[2][4] = {};
    for (int c = 0; c < 4; c++) {
        for (int i = tid; i < 64 * 64; i += 128) {
            int n = i >> 6, d = i & 63;
            kv[n][d] = g_v[(size_t)(b * 256 + c * 64 + n) * 1024 + h * 64 + d];
        }
        __syncthreads();
        #pragma unroll 4
        for (int n = 0; n < 64; n++) {
            float w0 = S[tr * 2 + 0][c * 64 + n];
            float w1 = S[tr * 2 + 1][c * 64 + n];
            float v0 = kv[n][dc * 4 + 0];
            float v1 = kv[n][dc * 4 + 1];
            float v2 = kv[n][dc * 4 + 2];
            float v3 = kv[n][dc * 4 + 3];
            acc[0][0] += w0 * v0; acc[0][1] += w0 * v1; acc[0][2] += w0 * v2; acc[0][3] += w0 * v3;
            acc[1][0] += w1 * v0; acc[1][1] += w1 * v1; acc[1][2] += w1 * v2; acc[1][3] += w1 * v3;
        }
        __syncthreads();
    }
    #pragma unroll
    for (int i = 0; i < 2; i++) {
        float4 r = make_float4(acc[i][0], acc[i][1], acc[i][2], acc[i][3]);
        *(float4*)&g_y[(size_t)(b * 1024 + t0 + tr * 2 + i) * 1024 + h * 64 + dc * 4] = r;
    }
}

// ================= silu(emb) @ Wemb + bemb =================
__global__ void __launch_bounds__(256) emb_gemv(const float* __restrict__ emb,
                                                const float* __restrict__ Wemb,
                                                const float* __restrict__ bemb) {
    int j = blockIdx.x * 256 + threadIdx.x;
    __shared__ float se[8][256];
    float acc[8] = {};
    for (int tt0 = 0; tt0 < 2048; tt0 += 256) {
        for (int i = threadIdx.x; i < 2048; i += 256) {
            int bb = i >> 8, t = i & 255;
            float e = emb[bb * 2048 + tt0 + t];
            se[bb][t] = e / (1.f + __expf(-e));
        }
        __syncthreads();
        #pragma unroll 4
        for (int t = 0; t < 256; t++) {
            float w = Wemb[(size_t)(tt0 + t) * 2048 + j];
            #pragma unroll
            for (int bb = 0; bb < 8; bb++) acc[bb] += se[bb][t] * w;
        }
        __syncthreads();
    }
    #pragma unroll
    for (int bb = 0; bb < 8; bb++)
        g_embo[bb * 2048 + j] = acc[bb] + bemb[j];
}

// ================= LN(y)*(1+scale)+shift -> silu -> bf16 hi/lo =================
__global__ void modulate_kernel(const float* __restrict__ gam, const float* __restrict__ bet) {
    int row = blockIdx.x;
    int b = row >> 10;
    const float* yr = g_y + (size_t)row * 1024;
    float sum = 0.f, sq = 0.f;
    for (int i = threadIdx.x; i < 1024; i += blockDim.x) {
        float v = yr[i];
        sum += v; sq += v * v;
    }
    __shared__ float s1[8], s2[8];
    #pragma unroll
    for (int o = 16; o; o >>= 1) {
        sum += __shfl_xor_sync(0xffffffffu, sum, o);
        sq  += __shfl_xor_sync(0xffffffffu, sq,  o);
    }
    int w = threadIdx.x >> 5, l = threadIdx.x & 31;
    if (l == 0) { s1[w] = sum; s2[w] = sq; }
    __syncthreads();
    __shared__ float mean_s, inv_s;
    if (threadIdx.x == 0) {
        float ts = 0.f, tq = 0.f;
        for (int i = 0; i < 8; i++) { ts += s1[i]; tq += s2[i]; }
        float mean = ts * (1.f / 1024.f);
        float var = tq * (1.f / 1024.f) - mean * mean;
        mean_s = mean;
        inv_s = rsqrtf(var + 1e-5f);
    }
    __syncthreads();
    float mean = mean_s, inv = inv_s;
    for (int i = threadIdx.x; i < 1024; i += blockDim.x) {
        float nv = (yr[i] - mean) * inv * gam[i] + bet[i];
        float sc = g_embo[b * 2048 + i];
        float sh = g_embo[b * 2048 + 1024 + i];
        float hv = nv * (1.f + sc) + sh;
        float sv = hv / (1.f + __expf(-hv));
        __nv_bfloat16 hi = __float2bfloat16(sv);
        g_hnh[(size_t)row * 1024 + i] = hi;
        g_hnl[(size_t)row * 1024 + i] = __float2bfloat16(sv - __bfloat162float(hi));
    }
}

// ================= launch =================
extern "C" void kernel_launch(void* const* d_in, const int* in_sizes, int n_in,
                              void* d_out, int out_size) {
    const float* x     = (const float*)d_in[0];
    const float* xf    = (const float*)d_in[1];
    const float* emb   = (const float*)d_in[2];
    const float* ln_g  = (const float*)d_in[3];
    const float* ln_b  = (const float*)d_in[4];
    const float* cln_g = (const float*)d_in[5];
    const float* cln_b = (const float*)d_in[6];
    const float* Wq    = (const float*)d_in[7];
    const float* bq    = (const float*)d_in[8];
    const float* Wk    = (const float*)d_in[9];
    const float* bk    = (const float*)d_in[10];
    const float* Wv    = (const float*)d_in[11];
    const float* bv    = (const float*)d_in[12];
    const float* sln_g = (const float*)d_in[13];
    const float* sln_b = (const float*)d_in[14];
    const float* Wemb  = (const float*)d_in[15];
    const float* bemb  = (const float*)d_in[16];
    const float* Wout  = (const float*)d_in[17];
    const float* bout  = (const float*)d_in[18];
    float* out = (float*)d_out;

    float *q, *k, *v;
    __nv_bfloat16 *xnh, *xnl, *xfh, *xfl, *hnh, *hnl;
    __nv_bfloat16 *wqh, *wql, *wkh, *wkl, *wvh, *wvl, *woh, *wol;
    cudaGetSymbolAddress((void**)&q,   g_q);
    cudaGetSymbolAddress((void**)&k,   g_k);
    cudaGetSymbolAddress((void**)&v,   g_v);
    cudaGetSymbolAddress((void**)&xnh, g_xnh);
    cudaGetSymbolAddress((void**)&xnl, g_xnl);
    cudaGetSymbolAddress((void**)&xfh, g_xfh);
    cudaGetSymbolAddress((void**)&xfl, g_xfl);
    cudaGetSymbolAddress((void**)&hnh, g_hnh);
    cudaGetSymbolAddress((void**)&hnl, g_hnl);
    cudaGetSymbolAddress((void**)&wqh, g_wqh);
    cudaGetSymbolAddress((void**)&wql, g_wql);
    cudaGetSymbolAddress((void**)&wkh, g_wkh);
    cudaGetSymbolAddress((void**)&wkl, g_wkl);
    cudaGetSymbolAddress((void**)&wvh, g_wvh);
    cudaGetSymbolAddress((void**)&wvl, g_wvl);
    cudaGetSymbolAddress((void**)&woh, g_woh);
    cudaGetSymbolAddress((void**)&wol, g_wol);

    static const int SMEM_GEMM = 2 * (int)STAGE_B;  // 81920
    cudaFuncSetAttribute(mma_gemm<false>, cudaFuncAttributeMaxDynamicSharedMemorySize, SMEM_GEMM);
    cudaFuncSetAttribute(mma_gemm<true>,  cudaFuncAttributeMaxDynamicSharedMemorySize, SMEM_GEMM);

    // 1) LayerNorms -> bf16 hi/lo
    ln_split_kernel<<<8192, 256>>>(x,  ln_g,  ln_b,  xnh, xnl, 1024);
    ln_split_kernel<<<2048, 256>>>(xf, cln_g, cln_b, xfh, xfl, 768);

    // 2) Weight transpose + split
    wsplit_kernel<<<dim3(32, 32), dim3(32, 8)>>>(Wq,   wqh, wql, 1024, 1024);
    wsplit_kernel<<<dim3(24, 32), dim3(32, 8)>>>(Wk,   wkh, wkl, 768,  1024);
    wsplit_kernel<<<dim3(24, 32), dim3(32, 8)>>>(Wv,   wvh, wvl, 768,  1024);
    wsplit_kernel<<<dim3(32, 32), dim3(32, 8)>>>(Wout, woh, wol, 1024, 1024);

    // 3) Projections on tensor cores (mma.sync)
    mma_gemm<false><<<dim3(8, 64), 256, SMEM_GEMM>>>(xnh, xnl, wqh, wql, bq, nullptr, q, 8192, 1024, 1024);
    mma_gemm<false><<<dim3(8, 16), 256, SMEM_GEMM>>>(xfh, xfl, wkh, wkl, bk, nullptr, k, 2048, 1024, 768);
    mma_gemm<false><<<dim3(8, 16), 256, SMEM_GEMM>>>(xfh, xfl, wvh, wvl, bv, nullptr, v, 2048, 1024, 768);

    // 4) Attention (SIMT fp32)
    attn_kernel<<<dim3(64, 16, 8), 128>>>();

    // 5) Stylization
    emb_gemv<<<8, 256>>>(emb, Wemb, bemb);
    modulate_kernel<<<8192, 256>>>(sln_g, sln_b);

    // 6) Output projection + residual
    mma_gemm<true><<<dim3(8, 64), 256, SMEM_GEMM>>>(hnh, hnl, woh, wol, bout, x, out, 8192, 1024, 1024);
}

// round 8
// speedup vs baseline: 2.9582x; 1.8712x over previous
#include <cuda_runtime.h>
#include <cuda_bf16.h>
#include <cstdint>
#include <cstddef>

// Problem constants: B=8, T=1024, D=1024, N=256, L=768, H=16, hd=64, TE=2048

// ================= helpers =================
__device__ __forceinline__ uint32_t smem_u32(const void* p) {
    uint32_t a;
    asm("{ .reg .u64 t; cvta.to.shared.u64 t, %1; cvt.u32.u64 %0, t; }" : "=r"(a) : "l"(p));
    return a;
}
#define CP_ASYNC16(smem, gptr) \
    asm volatile("cp.async.cg.shared.global [%0], [%1], 16;" :: "r"(smem), "l"(gptr))
#define CP_ASYNC_COMMIT() asm volatile("cp.async.commit_group;" ::: "memory")

__device__ __forceinline__ void ldsm_x4(uint32_t& r0, uint32_t& r1, uint32_t& r2, uint32_t& r3,
                                        uint32_t addr) {
    asm volatile("ldmatrix.sync.aligned.m8n8.x4.shared.b16 {%0,%1,%2,%3}, [%4];"
                 : "=r"(r0), "=r"(r1), "=r"(r2), "=r"(r3) : "r"(addr));
}
__device__ __forceinline__ void ldsm_x4_t(uint32_t& r0, uint32_t& r1, uint32_t& r2, uint32_t& r3,
                                          uint32_t addr) {
    asm volatile("ldmatrix.sync.aligned.m8n8.x4.trans.shared.b16 {%0,%1,%2,%3}, [%4];"
                 : "=r"(r0), "=r"(r1), "=r"(r2), "=r"(r3) : "r"(addr));
}
__device__ __forceinline__ void mma16816(float* d, const uint32_t* a, const uint32_t* b) {
    asm volatile("mma.sync.aligned.m16n8k16.row.col.f32.bf16.bf16.f32 "
                 "{%0,%1,%2,%3}, {%4,%5,%6,%7}, {%8,%9}, {%0,%1,%2,%3};"
                 : "+f"(d[0]), "+f"(d[1]), "+f"(d[2]), "+f"(d[3])
                 : "r"(a[0]), "r"(a[1]), "r"(a[2]), "r"(a[3]), "r"(b[0]), "r"(b[1]));
}
__device__ __forceinline__ uint32_t pack_bf16x2(float a, float b) {
    __nv_bfloat162 h = __floats2bfloat162_rn(a, b);
    return *(uint32_t*)&h;
}

// ================= scratch (device globals) =================
__device__ float g_y  [8192u*1024u];
__device__ float g_embo[8u*2048u];
__device__ __nv_bfloat16 g_xnh[8192u*1024u];   // LN(x) bf16
__device__ __nv_bfloat16 g_xfh[2048u*768u];    // LN(xf) bf16
__device__ __nv_bfloat16 g_qh [8192u*1024u];   // q bf16
__device__ __nv_bfloat16 g_kh [2048u*1024u];   // k bf16
__device__ __nv_bfloat16 g_vh [2048u*1024u];   // v bf16
__device__ __nv_bfloat16 g_hnh[8192u*1024u];   // silu(mod) bf16
__device__ __nv_bfloat16 g_wq [1024u*1024u];   // Wq^T bf16 [N,K]
__device__ __nv_bfloat16 g_wk [1024u*768u];
__device__ __nv_bfloat16 g_wv [1024u*768u];
__device__ __nv_bfloat16 g_wo [1024u*1024u];

// ================= LayerNorm -> bf16 =================
__global__ void ln_bf16_kernel(const float* __restrict__ X, const float* __restrict__ gam,
                               const float* __restrict__ bet, __nv_bfloat16* __restrict__ O, int Wd) {
    int row = blockIdx.x;
    const float* xr = X + (size_t)row * Wd;
    float sum = 0.f, sq = 0.f;
    for (int i = threadIdx.x; i < Wd; i += blockDim.x) {
        float v = xr[i];
        sum += v; sq += v * v;
    }
    __shared__ float s1[8], s2[8];
    #pragma unroll
    for (int o = 16; o; o >>= 1) {
        sum += __shfl_xor_sync(0xffffffffu, sum, o);
        sq  += __shfl_xor_sync(0xffffffffu, sq,  o);
    }
    int w = threadIdx.x >> 5, l = threadIdx.x & 31;
    if (l == 0) { s1[w] = sum; s2[w] = sq; }
    __syncthreads();
    __shared__ float mean_s, inv_s;
    if (threadIdx.x == 0) {
        float ts = 0.f, tq = 0.f;
        int nw = blockDim.x >> 5;
        for (int i = 0; i < nw; i++) { ts += s1[i]; tq += s2[i]; }
        float mean = ts / Wd;
        float var = tq / Wd - mean * mean;
        mean_s = mean;
        inv_s = rsqrtf(var + 1e-5f);
    }
    __syncthreads();
    float mean = mean_s, inv = inv_s;
    for (int i = threadIdx.x; i < Wd; i += blockDim.x)
        O[(size_t)row * Wd + i] = __float2bfloat16((xr[i] - mean) * inv * gam[i] + bet[i]);
}

// ================= weight transpose: W[K,N] fp32 -> T[N,K] bf16 =================
__global__ void wsplit_kernel(const float* __restrict__ W, __nv_bfloat16* __restrict__ Th,
                              int K, int Nn) {
    __shared__ float t[32][33];
    int k0 = blockIdx.x * 32, n0 = blockIdx.y * 32;
    int tx = threadIdx.x, ty = threadIdx.y;  // (32, 8)
    #pragma unroll
    for (int r = ty; r < 32; r += 8)
        t[r][tx] = W[(size_t)(k0 + r) * Nn + n0 + tx];
    __syncthreads();
    #pragma unroll
    for (int r = ty; r < 32; r += 8)
        Th[(size_t)(n0 + r) * K + k0 + tx] = __float2bfloat16(t[tx][r]);
}

// ================= mma.sync bf16 GEMM =================
// C[M,Nn] = A[M,K] @ Bw[Nn,K]^T + bias (+ R). MODE: 0=f32, 1=f32+residual, 2=bf16 out.
// 128x128 tile, 256 threads (2x4 warps, 64x32/warp), BK=32, cp.async double buffer.
static constexpr uint32_t TSTRIDE = 80;            // 32 bf16 + 8 pad bytes
static constexpr uint32_t TILE_B  = 128 * TSTRIDE; // 10240
static constexpr uint32_t STAGE_B = 2 * TILE_B;    // 20480 (A, B)

template<int MODE>
__global__ void __launch_bounds__(256) mma_gemm(
    const __nv_bfloat16* __restrict__ A, const __nv_bfloat16* __restrict__ Bw,
    const float* __restrict__ bias, const float* __restrict__ R,
    float* __restrict__ Cf, __nv_bfloat16* __restrict__ Cb, int M, int Nn, int K) {
    extern __shared__ char smem[];
    uint32_t sbase = smem_u32(smem);

    int tid = threadIdx.x, wid = tid >> 5, lane = tid & 31;
    int wm = wid >> 2, wn = wid & 3;          // warp tile origin: (wm*64, wn*32)
    int bm = blockIdx.y * 128, bn = blockIdx.x * 128;

    const __nv_bfloat16* gA = A  + (size_t)bm * K;
    const __nv_bfloat16* gB = Bw + (size_t)bn * K;

    float acc[4][4][4] = {};   // [mt][nt][reg]
    const int NC = K >> 5;

    auto load_stage = [&](int c) {
        uint32_t sb = sbase + (uint32_t)(c & 1) * STAGE_B;
        int kc = c * 32;
        #pragma unroll
        for (int i = tid; i < 512; i += 256) {
            int r = i >> 2, q = i & 3;
            CP_ASYNC16(sb + r * TSTRIDE + q * 16,          gA + (size_t)r * K + kc + q * 8);
            CP_ASYNC16(sb + TILE_B + r * TSTRIDE + q * 16, gB + (size_t)r * K + kc + q * 8);
        }
    };

    load_stage(0);
    CP_ASYNC_COMMIT();

    uint32_t aRow = (uint32_t)(wm * 64) + ((lane >> 3) & 1) * 8 + (lane & 7);
    uint32_t aCol = (lane >> 4) * 16;                       // bytes
    uint32_t bRow = (uint32_t)(wn * 32) + ((lane >> 4) * 8) + (lane & 7);
    uint32_t bCol = ((lane >> 3) & 1) * 16;                 // bytes

    for (int c = 0; c < NC; c++) {
        if (c + 1 < NC) { load_stage(c + 1); CP_ASYNC_COMMIT(); }
        if (c + 1 < NC) asm volatile("cp.async.wait_group 1;" ::: "memory");
        else            asm volatile("cp.async.wait_group 0;" ::: "memory");
        __syncthreads();

        uint32_t sb = sbase + (uint32_t)(c & 1) * STAGE_B;
        #pragma unroll
        for (int kk = 0; kk < 2; kk++) {
            uint32_t kOff = kk * 32;
            uint32_t ah[4][4], bh[4][2];
            #pragma unroll
            for (int mt = 0; mt < 4; mt++) {
                uint32_t ad = sb + (aRow + mt * 16) * TSTRIDE + aCol + kOff;
                ldsm_x4(ah[mt][0], ah[mt][1], ah[mt][2], ah[mt][3], ad);
            }
            #pragma unroll
            for (int np = 0; np < 2; np++) {
                uint32_t bd = sb + TILE_B + (bRow + np * 16) * TSTRIDE + bCol + kOff;
                ldsm_x4(bh[np*2][0], bh[np*2][1], bh[np*2+1][0], bh[np*2+1][1], bd);
            }
            #pragma unroll
            for (int mt = 0; mt < 4; mt++)
                #pragma unroll
                for (int nt = 0; nt < 4; nt++)
                    mma16816(acc[mt][nt], ah[mt], bh[nt]);
        }
        __syncthreads();
    }

    // ---- epilogue ----
    int g = lane >> 2, tg = lane & 3;
    #pragma unroll
    for (int mt = 0; mt < 4; mt++) {
        int r0 = bm + wm * 64 + mt * 16 + g;
        #pragma unroll
        for (int nt = 0; nt < 4; nt++) {
            int col = bn + wn * 32 + nt * 8 + tg * 2;
            float b0 = bias[col], b1 = bias[col + 1];
            size_t o0 = (size_t)r0 * Nn + col;
            size_t o1 = (size_t)(r0 + 8) * Nn + col;
            float v00 = acc[mt][nt][0] + b0, v01 = acc[mt][nt][1] + b1;
            float v10 = acc[mt][nt][2] + b0, v11 = acc[mt][nt][3] + b1;
            if (MODE == 2) {
                *(uint32_t*)&Cb[o0] = pack_bf16x2(v00, v01);
                *(uint32_t*)&Cb[o1] = pack_bf16x2(v10, v11);
            } else {
                if (MODE == 1) {
                    float2 r00 = *(const float2*)&R[o0];
                    float2 r11 = *(const float2*)&R[o1];
                    v00 += r00.x; v01 += r00.y; v10 += r11.x; v11 += r11.y;
                }
                *(float2*)&Cf[o0] = make_float2(v00, v01);
                *(float2*)&Cf[o1] = make_float2(v10, v11);
            }
        }
    }
}

// ================= FA2-style attention (mma.sync bf16) =================
// grid (T/64=16, H=16, B=8), 128 threads (4 warps, 16 q-rows each).
// K,V (256x64 per (b,h)) staged in SMEM (stride 72 bf16 = 144 B), Q frags in regs.
__global__ void __launch_bounds__(128) attn_mma_kernel() {
    extern __shared__ char smem[];
    __nv_bfloat16* Ks = (__nv_bfloat16*)smem;          // 256 x 72
    __nv_bfloat16* Vs = Ks + 256 * 72;                 // 256 x 72
    uint32_t sbK = smem_u32(Ks), sbV = smem_u32(Vs);

    int tid = threadIdx.x, w = tid >> 5, lane = tid & 31;
    int b = blockIdx.z, h = blockIdx.y, q0 = blockIdx.x * 64;
    int g = lane >> 2, t4 = lane & 3;

    // stage K, V
    for (int i = tid; i < 2048; i += 128) {
        int r = i >> 3, q8 = i & 7;
        size_t go = (size_t)(b * 256 + r) * 1024 + h * 64 + q8 * 8;
        *(uint4*)(Ks + r * 72 + q8 * 8) = *(const uint4*)(g_kh + go);
        *(uint4*)(Vs + r * 72 + q8 * 8) = *(const uint4*)(g_vh + go);
    }
    __syncthreads();

    // Q fragments (16 rows per warp) straight from gmem
    uint32_t aq[4][4];
    const __nv_bfloat16* qb = g_qh + (size_t)(b * 1024 + q0 + w * 16) * 1024 + h * 64;
    #pragma unroll
    for (int ks = 0; ks < 4; ks++) {
        aq[ks][0] = *(const uint32_t*)(qb + (size_t)g * 1024       + ks * 16 + 2 * t4);
        aq[ks][1] = *(const uint32_t*)(qb + (size_t)(g + 8) * 1024 + ks * 16 + 2 * t4);
        aq[ks][2] = *(const uint32_t*)(qb + (size_t)g * 1024       + ks * 16 + 8 + 2 * t4);
        aq[ks][3] = *(const uint32_t*)(qb + (size_t)(g + 8) * 1024 + ks * 16 + 8 + 2 * t4);
    }

    float o[8][4] = {};
    float m0 = -1e30f, m1 = -1e30f, l0 = 0.f, l1 = 0.f;

    uint32_t bRowOff = ((lane >> 4) * 8 + (lane & 7));           // score-B lane row
    uint32_t bColOff = ((lane >> 3) & 1) * 16;                   // score-B lane col bytes
    uint32_t vRowOff = (((lane >> 3) & 1) * 8 + (lane & 7));     // V lane row
    uint32_t vColOff = (lane >> 4) * 16;                         // V lane col bytes

    for (int c = 0; c < 4; c++) {
        int n0 = c * 64;
        float s[8][4] = {};
        #pragma unroll
        for (int ks = 0; ks < 4; ks++) {
            #pragma unroll
            for (int np = 0; np < 4; np++) {
                uint32_t r0, r1, r2, r3;
                uint32_t bd = sbK + (n0 + np * 16 + bRowOff) * 144 + bColOff + ks * 32;
                ldsm_x4(r0, r1, r2, r3, bd);
                uint32_t blo[2] = {r0, r1}, bhi[2] = {r2, r3};
                mma16816(s[np * 2],     aq[ks], blo);
                mma16816(s[np * 2 + 1], aq[ks], bhi);
            }
        }
        // scale + online softmax
        float mx0 = -1e30f, mx1 = -1e30f;
        #pragma unroll
        for (int j = 0; j < 8; j++) {
            #pragma unroll
            for (int r = 0; r < 4; r++) s[j][r] *= 0.125f;
            mx0 = fmaxf(mx0, fmaxf(s[j][0], s[j][1]));
            mx1 = fmaxf(mx1, fmaxf(s[j][2], s[j][3]));
        }
        mx0 = fmaxf(mx0, __shfl_xor_sync(0xffffffffu, mx0, 1));
        mx0 = fmaxf(mx0, __shfl_xor_sync(0xffffffffu, mx0, 2));
        mx1 = fmaxf(mx1, __shfl_xor_sync(0xffffffffu, mx1, 1));
        mx1 = fmaxf(mx1, __shfl_xor_sync(0xffffffffu, mx1, 2));
        float nm0 = fmaxf(m0, mx0), nm1 = fmaxf(m1, mx1);
        float al0 = __expf(m0 - nm0), al1 = __expf(m1 - nm1);
        m0 = nm0; m1 = nm1;
        float sum0 = 0.f, sum1 = 0.f;
        #pragma unroll
        for (int j = 0; j < 8; j++) {
            s[j][0] = __expf(s[j][0] - m0);
            s[j][1] = __expf(s[j][1] - m0);
            s[j][2] = __expf(s[j][2] - m1);
            s[j][3] = __expf(s[j][3] - m1);
            sum0 += s[j][0] + s[j][1];
            sum1 += s[j][2] + s[j][3];
        }
        sum0 += __shfl_xor_sync(0xffffffffu, sum0, 1);
        sum0 += __shfl_xor_sync(0xffffffffu, sum0, 2);
        sum1 += __shfl_xor_sync(0xffffffffu, sum1, 1);
        sum1 += __shfl_xor_sync(0xffffffffu, sum1, 2);
        l0 = l0 * al0 + sum0;
        l1 = l1 * al1 + sum1;
        #pragma unroll
        for (int dt = 0; dt < 8; dt++) {
            o[dt][0] *= al0; o[dt][1] *= al0;
            o[dt][2] *= al1; o[dt][3] *= al1;
        }
        // P frags (bf16) for PV
        uint32_t pa[4][4];
        #pragma unroll
        for (int j = 0; j < 4; j++) {
            pa[j][0] = pack_bf16x2(s[2*j][0],   s[2*j][1]);
            pa[j][1] = pack_bf16x2(s[2*j][2],   s[2*j][3]);
            pa[j][2] = pack_bf16x2(s[2*j+1][0], s[2*j+1][1]);
            pa[j][3] = pack_bf16x2(s[2*j+1][2], s[2*j+1][3]);
        }
        #pragma unroll
        for (int j = 0; j < 4; j++) {
            #pragma unroll
            for (int dp = 0; dp < 4; dp++) {
                uint32_t r0, r1, r2, r3;
                uint32_t vd = sbV + (n0 + j * 16 + vRowOff) * 144 + dp * 32 + vColOff;
                ldsm_x4_t(r0, r1, r2, r3, vd);
                uint32_t blo[2] = {r0, r1}, bhi[2] = {r2, r3};
                mma16816(o[dp * 2],     pa[j], blo);
                mma16816(o[dp * 2 + 1], pa[j], bhi);
            }
        }
    }
    float inv0 = 1.f / l0, inv1 = 1.f / l1;
    float* yb = g_y + (size_t)(b * 1024 + q0 + w * 16) * 1024 + h * 64;
    #pragma unroll
    for (int dt = 0; dt < 8; dt++) {
        int col = dt * 8 + 2 * t4;
        *(float2*)(yb + (size_t)g * 1024 + col)       = make_float2(o[dt][0] * inv0, o[dt][1] * inv0);
        *(float2*)(yb + (size_t)(g + 8) * 1024 + col) = make_float2(o[dt][2] * inv1, o[dt][3] * inv1);
    }
}

// ================= silu(emb) @ Wemb + bemb =================
__global__ void __launch_bounds__(256) emb_gemv(const float* __restrict__ emb,
                                                const float* __restrict__ Wemb,
                                                const float* __restrict__ bemb) {
    int j = blockIdx.x * 256 + threadIdx.x;
    __shared__ float se[8][256];
    float acc[8] = {};
    for (int tt0 = 0; tt0 < 2048; tt0 += 256) {
        for (int i = threadIdx.x; i < 2048; i += 256) {
            int bb = i >> 8, t = i & 255;
            float e = emb[bb * 2048 + tt0 + t];
            se[bb][t] = e / (1.f + __expf(-e));
        }
        __syncthreads();
        #pragma unroll 4
        for (int t = 0; t < 256; t++) {
            float w = Wemb[(size_t)(tt0 + t) * 2048 + j];
            #pragma unroll
            for (int bb = 0; bb < 8; bb++) acc[bb] += se[bb][t] * w;
        }
        __syncthreads();
    }
    #pragma unroll
    for (int bb = 0; bb < 8; bb++)
        g_embo[bb * 2048 + j] = acc[bb] + bemb[j];
}

// ================= LN(y)*(1+scale)+shift -> silu -> bf16 =================
__global__ void modulate_kernel(const float* __restrict__ gam, const float* __restrict__ bet) {
    int row = blockIdx.x;
    int b = row >> 10;
    const float* yr = g_y + (size_t)row * 1024;
    float sum = 0.f, sq = 0.f;
    for (int i = threadIdx.x; i < 1024; i += blockDim.x) {
        float v = yr[i];
        sum += v; sq += v * v;
    }
    __shared__ float s1[8], s2[8];
    #pragma unroll
    for (int o = 16; o; o >>= 1) {
        sum += __shfl_xor_sync(0xffffffffu, sum, o);
        sq  += __shfl_xor_sync(0xffffffffu, sq,  o);
    }
    int w = threadIdx.x >> 5, l = threadIdx.x & 31;
    if (l == 0) { s1[w] = sum; s2[w] = sq; }
    __syncthreads();
    __shared__ float mean_s, inv_s;
    if (threadIdx.x == 0) {
        float ts = 0.f, tq = 0.f;
        for (int i = 0; i < 8; i++) { ts += s1[i]; tq += s2[i]; }
        float mean = ts * (1.f / 1024.f);
        float var = tq * (1.f / 1024.f) - mean * mean;
        mean_s = mean;
        inv_s = rsqrtf(var + 1e-5f);
    }
    __syncthreads();
    float mean = mean_s, inv = inv_s;
    for (int i = threadIdx.x; i < 1024; i += blockDim.x) {
        float nv = (yr[i] - mean) * inv * gam[i] + bet[i];
        float sc = g_embo[b * 2048 + i];
        float sh = g_embo[b * 2048 + 1024 + i];
        float hv = nv * (1.f + sc) + sh;
        g_hnh[(size_t)row * 1024 + i] = __float2bfloat16(hv / (1.f + __expf(-hv)));
    }
}

// ================= launch =================
extern "C" void kernel_launch(void* const* d_in, const int* in_sizes, int n_in,
                              void* d_out, int out_size) {
    const float* x     = (const float*)d_in[0];
    const float* xf    = (const float*)d_in[1];
    const float* emb   = (const float*)d_in[2];
    const float* ln_g  = (const float*)d_in[3];
    const float* ln_b  = (const float*)d_in[4];
    const float* cln_g = (const float*)d_in[5];
    const float* cln_b = (const float*)d_in[6];
    const float* Wq    = (const float*)d_in[7];
    const float* bq    = (const float*)d_in[8];
    const float* Wk    = (const float*)d_in[9];
    const float* bk    = (const float*)d_in[10];
    const float* Wv    = (const float*)d_in[11];
    const float* bv    = (const float*)d_in[12];
    const float* sln_g = (const float*)d_in[13];
    const float* sln_b = (const float*)d_in[14];
    const float* Wemb  = (const float*)d_in[15];
    const float* bemb  = (const float*)d_in[16];
    const float* Wout  = (const float*)d_in[17];
    const float* bout  = (const float*)d_in[18];
    float* out = (float*)d_out;

    __nv_bfloat16 *xnh, *xfh, *qh, *kh, *vh, *hnh, *wq, *wk, *wv, *wo;
    cudaGetSymbolAddress((void**)&xnh, g_xnh);
    cudaGetSymbolAddress((void**)&xfh, g_xfh);
    cudaGetSymbolAddress((void**)&qh,  g_qh);
    cudaGetSymbolAddress((void**)&kh,  g_kh);
    cudaGetSymbolAddress((void**)&vh,  g_vh);
    cudaGetSymbolAddress((void**)&hnh, g_hnh);
    cudaGetSymbolAddress((void**)&wq,  g_wq);
    cudaGetSymbolAddress((void**)&wk,  g_wk);
    cudaGetSymbolAddress((void**)&wv,  g_wv);
    cudaGetSymbolAddress((void**)&wo,  g_wo);

    static const int SMEM_GEMM = 2 * (int)STAGE_B;   // 40960
    static const int SMEM_ATTN = 2 * 256 * 144;      // 73728
    cudaFuncSetAttribute(mma_gemm<0>, cudaFuncAttributeMaxDynamicSharedMemorySize, SMEM_GEMM);
    cudaFuncSetAttribute(mma_gemm<1>, cudaFuncAttributeMaxDynamicSharedMemorySize, SMEM_GEMM);
    cudaFuncSetAttribute(mma_gemm<2>, cudaFuncAttributeMaxDynamicSharedMemorySize, SMEM_GEMM);
    cudaFuncSetAttribute(attn_mma_kernel, cudaFuncAttributeMaxDynamicSharedMemorySize, SMEM_ATTN);

    // 1) LayerNorms -> bf16
    ln_bf16_kernel<<<8192, 256>>>(x,  ln_g,  ln_b,  xnh, 1024);
    ln_bf16_kernel<<<2048, 256>>>(xf, cln_g, cln_b, xfh, 768);

    // 2) Weight transpose -> bf16
    wsplit_kernel<<<dim3(32, 32), dim3(32, 8)>>>(Wq,   wq, 1024, 1024);
    wsplit_kernel<<<dim3(24, 32), dim3(32, 8)>>>(Wk,   wk, 768,  1024);
    wsplit_kernel<<<dim3(24, 32), dim3(32, 8)>>>(Wv,   wv, 768,  1024);
    wsplit_kernel<<<dim3(32, 32), dim3(32, 8)>>>(Wout, wo, 1024, 1024);

    // 3) Projections -> bf16 outputs
    mma_gemm<2><<<dim3(8, 64), 256, SMEM_GEMM>>>(xnh, wq, bq, nullptr, nullptr, qh, 8192, 1024, 1024);
    mma_gemm<2><<<dim3(8, 16), 256, SMEM_GEMM>>>(xfh, wk, bk, nullptr, nullptr, kh, 2048, 1024, 768);
    mma_gemm<2><<<dim3(8, 16), 256, SMEM_GEMM>>>(xfh, wv, bv, nullptr, nullptr, vh, 2048, 1024, 768);

    // 4) Attention (tensor cores, online softmax)
    attn_mma_kernel<<<dim3(16, 16, 8), 128, SMEM_ATTN>>>();

    // 5) Stylization
    emb_gemv<<<8, 256>>>(emb, Wemb, bemb);
    modulate_kernel<<<8192, 256>>>(sln_g, sln_b);

    // 6) Output projection + residual (fp32 out)
    mma_gemm<1><<<dim3(8, 64), 256, SMEM_GEMM>>>(hnh, wo, bout, x, out, nullptr, 8192, 1024, 1024);
}

// round 9
// speedup vs baseline: 4.1247x; 1.3944x over previous
#include <cuda_runtime.h>
#include <cuda_bf16.h>
#include <cstdint>
#include <cstddef>

// Problem constants: B=8, T=1024, D=1024, N=256, L=768, H=16, hd=64, TE=2048

// ================= helpers =================
__device__ __forceinline__ uint32_t smem_u32(const void* p) {
    uint32_t a;
    asm("{ .reg .u64 t; cvta.to.shared.u64 t, %1; cvt.u32.u64 %0, t; }" : "=r"(a) : "l"(p));
    return a;
}
#define CP_ASYNC16(smem, gptr) \
    asm volatile("cp.async.cg.shared.global [%0], [%1], 16;" :: "r"(smem), "l"(gptr))
#define CP_ASYNC_COMMIT() asm volatile("cp.async.commit_group;" ::: "memory")

__device__ __forceinline__ void ldsm_x4(uint32_t& r0, uint32_t& r1, uint32_t& r2, uint32_t& r3,
                                        uint32_t addr) {
    asm volatile("ldmatrix.sync.aligned.m8n8.x4.shared.b16 {%0,%1,%2,%3}, [%4];"
                 : "=r"(r0), "=r"(r1), "=r"(r2), "=r"(r3) : "r"(addr));
}
__device__ __forceinline__ void ldsm_x4_t(uint32_t& r0, uint32_t& r1, uint32_t& r2, uint32_t& r3,
                                          uint32_t addr) {
    asm volatile("ldmatrix.sync.aligned.m8n8.x4.trans.shared.b16 {%0,%1,%2,%3}, [%4];"
                 : "=r"(r0), "=r"(r1), "=r"(r2), "=r"(r3) : "r"(addr));
}
__device__ __forceinline__ void mma16816(float* d, const uint32_t* a, const uint32_t* b) {
    asm volatile("mma.sync.aligned.m16n8k16.row.col.f32.bf16.bf16.f32 "
                 "{%0,%1,%2,%3}, {%4,%5,%6,%7}, {%8,%9}, {%0,%1,%2,%3};"
                 : "+f"(d[0]), "+f"(d[1]), "+f"(d[2]), "+f"(d[3])
                 : "r"(a[0]), "r"(a[1]), "r"(a[2]), "r"(a[3]), "r"(b[0]), "r"(b[1]));
}
__device__ __forceinline__ uint32_t pack_bf16x2(float a, float b) {
    __nv_bfloat162 h = __floats2bfloat162_rn(a, b);
    return *(uint32_t*)&h;
}

// ================= scratch (device globals) =================
__device__ float g_y  [8192u*1024u];
__device__ float g_embo[8u*2048u];
__device__ float g_embp[8u*8u*2048u];          // split-K partials [ky][b][j]
__device__ __nv_bfloat16 g_xnh[8192u*1024u];   // LN(x) bf16
__device__ __nv_bfloat16 g_xfh[2048u*768u];    // LN(xf) bf16
__device__ __nv_bfloat16 g_qh [8192u*1024u];
__device__ __nv_bfloat16 g_kh [2048u*1024u];
__device__ __nv_bfloat16 g_vh [2048u*1024u];
__device__ __nv_bfloat16 g_hnh[8192u*1024u];
__device__ __nv_bfloat16 g_wq [1024u*1024u];   // W^T bf16 [N,K]
__device__ __nv_bfloat16 g_wk [1024u*768u];
__device__ __nv_bfloat16 g_wv [1024u*768u];
__device__ __nv_bfloat16 g_wo [1024u*1024u];

// ================= merged LayerNorm -> bf16 (x rows then xf rows) =================
__global__ void ln_all_kernel(const float* __restrict__ x, const float* __restrict__ ln_g,
                              const float* __restrict__ ln_b,
                              const float* __restrict__ xf, const float* __restrict__ cg,
                              const float* __restrict__ cb) {
    int row = blockIdx.x;
    const float* X; const float* gam; const float* bet; __nv_bfloat16* O; int Wd;
    if (row < 8192) { X = x; gam = ln_g; bet = ln_b; O = g_xnh; Wd = 1024; }
    else { row -= 8192; X = xf; gam = cg; bet = cb; O = g_xfh; Wd = 768; }
    const float* xr = X + (size_t)row * Wd;
    float sum = 0.f, sq = 0.f;
    for (int i = threadIdx.x; i < Wd; i += blockDim.x) {
        float v = xr[i];
        sum += v; sq += v * v;
    }
    __shared__ float s1[8], s2[8];
    #pragma unroll
    for (int o = 16; o; o >>= 1) {
        sum += __shfl_xor_sync(0xffffffffu, sum, o);
        sq  += __shfl_xor_sync(0xffffffffu, sq,  o);
    }
    int w = threadIdx.x >> 5, l = threadIdx.x & 31;
    if (l == 0) { s1[w] = sum; s2[w] = sq; }
    __syncthreads();
    __shared__ float mean_s, inv_s;
    if (threadIdx.x == 0) {
        float ts = 0.f, tq = 0.f;
        for (int i = 0; i < 8; i++) { ts += s1[i]; tq += s2[i]; }
        float mean = ts / Wd;
        float var = tq / Wd - mean * mean;
        mean_s = mean;
        inv_s = rsqrtf(var + 1e-5f);
    }
    __syncthreads();
    float mean = mean_s, inv = inv_s;
    for (int i = threadIdx.x; i < Wd; i += blockDim.x)
        O[(size_t)row * Wd + i] = __float2bfloat16((xr[i] - mean) * inv * gam[i] + bet[i]);
}

// ================= merged weight transpose: 4 weights in one launch =================
__global__ void wsplit_all_kernel(const float* __restrict__ Wq, const float* __restrict__ Wk,
                                  const float* __restrict__ Wv, const float* __restrict__ Wo) {
    int idx = blockIdx.x;
    const float* W; __nv_bfloat16* Th; int K, kt;
    if (idx < 1024)      { W = Wq; Th = g_wq; K = 1024; kt = 32; }
    else if (idx < 1792) { W = Wk; Th = g_wk; K = 768;  kt = 24; idx -= 1024; }
    else if (idx < 2560) { W = Wv; Th = g_wv; K = 768;  kt = 24; idx -= 1792; }
    else                 { W = Wo; Th = g_wo; K = 1024; kt = 32; idx -= 2560; }
    int k0 = (idx % kt) * 32, n0 = (idx / kt) * 32;
    const int Nn = 1024;
    __shared__ float t[32][33];
    int tx = threadIdx.x, ty = threadIdx.y;  // (32, 8)
    #pragma unroll
    for (int r = ty; r < 32; r += 8)
        t[r][tx] = W[(size_t)(k0 + r) * Nn + n0 + tx];
    __syncthreads();
    #pragma unroll
    for (int r = ty; r < 32; r += 8)
        Th[(size_t)(n0 + r) * K + k0 + tx] = __float2bfloat16(t[tx][r]);
}

// ================= mma.sync bf16 GEMM body (3-stage cp.async) =================
static constexpr uint32_t TSTRIDE = 80;            // 32 bf16 + 8 pad bytes
static constexpr uint32_t TILE_B  = 128 * TSTRIDE; // 10240
static constexpr uint32_t STAGE_B = 2 * TILE_B;    // 20480 (A, B)
static constexpr int GEMM_SMEM = 3 * (int)STAGE_B; // 61440

// MODE: 1 = f32 out + residual, 2 = bf16 out
template<int MODE>
__device__ __forceinline__ void gemm_body(
    const __nv_bfloat16* __restrict__ A, const __nv_bfloat16* __restrict__ Bw,
    const float* __restrict__ bias, const float* __restrict__ R,
    float* __restrict__ Cf, __nv_bfloat16* __restrict__ Cb,
    int bm, int bn, int Nn, int K, uint32_t sbase) {
    int tid = threadIdx.x, wid = tid >> 5, lane = tid & 31;
    int wm = wid >> 2, wn = wid & 3;

    const __nv_bfloat16* gA = A  + (size_t)bm * K;
    const __nv_bfloat16* gB = Bw + (size_t)bn * K;

    float acc[4][4][4] = {};
    const int NC = K >> 5;

    auto load_stage = [&](int c) {
        uint32_t sb = sbase + (uint32_t)(c % 3) * STAGE_B;
        int kc = c * 32;
        #pragma unroll
        for (int i = tid; i < 512; i += 256) {
            int r = i >> 2, q = i & 3;
            CP_ASYNC16(sb + r * TSTRIDE + q * 16,          gA + (size_t)r * K + kc + q * 8);
            CP_ASYNC16(sb + TILE_B + r * TSTRIDE + q * 16, gB + (size_t)r * K + kc + q * 8);
        }
    };

    load_stage(0); CP_ASYNC_COMMIT();
    if (NC > 1) load_stage(1);
    CP_ASYNC_COMMIT();

    uint32_t aRow = (uint32_t)(wm * 64) + ((lane >> 3) & 1) * 8 + (lane & 7);
    uint32_t aCol = (lane >> 4) * 16;
    uint32_t bRow = (uint32_t)(wn * 32) + ((lane >> 4) * 8) + (lane & 7);
    uint32_t bCol = ((lane >> 3) & 1) * 16;

    for (int c = 0; c < NC; c++) {
        asm volatile("cp.async.wait_group 1;" ::: "memory");
        __syncthreads();
        if (c + 2 < NC) load_stage(c + 2);
        CP_ASYNC_COMMIT();

        uint32_t sb = sbase + (uint32_t)(c % 3) * STAGE_B;
        #pragma unroll
        for (int kk = 0; kk < 2; kk++) {
            uint32_t kOff = kk * 32;
            uint32_t ah[4][4], bh[4][2];
            #pragma unroll
            for (int mt = 0; mt < 4; mt++) {
                uint32_t ad = sb + (aRow + mt * 16) * TSTRIDE + aCol + kOff;
                ldsm_x4(ah[mt][0], ah[mt][1], ah[mt][2], ah[mt][3], ad);
            }
            #pragma unroll
            for (int np = 0; np < 2; np++) {
                uint32_t bd = sb + TILE_B + (bRow + np * 16) * TSTRIDE + bCol + kOff;
                ldsm_x4(bh[np*2][0], bh[np*2][1], bh[np*2+1][0], bh[np*2+1][1], bd);
            }
            #pragma unroll
            for (int mt = 0; mt < 4; mt++)
                #pragma unroll
                for (int nt = 0; nt < 4; nt++)
                    mma16816(acc[mt][nt], ah[mt], bh[nt]);
        }
        __syncthreads();
    }

    int g = lane >> 2, tg = lane & 3;
    #pragma unroll
    for (int mt = 0; mt < 4; mt++) {
        int r0 = bm + wm * 64 + mt * 16 + g;
        #pragma unroll
        for (int nt = 0; nt < 4; nt++) {
            int col = bn + wn * 32 + nt * 8 + tg * 2;
            float b0 = bias[col], b1 = bias[col + 1];
            size_t o0 = (size_t)r0 * Nn + col;
            size_t o1 = (size_t)(r0 + 8) * Nn + col;
            float v00 = acc[mt][nt][0] + b0, v01 = acc[mt][nt][1] + b1;
            float v10 = acc[mt][nt][2] + b0, v11 = acc[mt][nt][3] + b1;
            if (MODE == 2) {
                *(uint32_t*)&Cb[o0] = pack_bf16x2(v00, v01);
                *(uint32_t*)&Cb[o1] = pack_bf16x2(v10, v11);
            } else {
                float2 r00 = *(const float2*)&R[o0];
                float2 r11 = *(const float2*)&R[o1];
                *(float2*)&Cf[o0] = make_float2(v00 + r00.x, v01 + r00.y);
                *(float2*)&Cf[o1] = make_float2(v10 + r11.x, v11 + r11.y);
            }
        }
    }
}

// merged q/k/v projection GEMM: 768 tiles in one launch
__global__ void __launch_bounds__(256) qkv_gemm_kernel(
    const float* __restrict__ bq, const float* __restrict__ bk, const float* __restrict__ bv) {
    extern __shared__ char smem[];
    uint32_t sbase = smem_u32(smem);
    int tile = blockIdx.x;
    const __nv_bfloat16 *A, *Bw; const float* bias; __nv_bfloat16* Cb; int K;
    int bm, bn;
    if (tile < 512) {            // Q: 64 x 8 tiles
        A = g_xnh; Bw = g_wq; bias = bq; Cb = g_qh; K = 1024;
        bm = (tile >> 3) * 128; bn = (tile & 7) * 128;
    } else if (tile < 640) {     // K: 16 x 8 tiles
        tile -= 512;
        A = g_xfh; Bw = g_wk; bias = bk; Cb = g_kh; K = 768;
        bm = (tile >> 3) * 128; bn = (tile & 7) * 128;
    } else {                     // V: 16 x 8 tiles
        tile -= 640;
        A = g_xfh; Bw = g_wv; bias = bv; Cb = g_vh; K = 768;
        bm = (tile >> 3) * 128; bn = (tile & 7) * 128;
    }
    gemm_body<2>(A, Bw, bias, nullptr, nullptr, Cb, bm, bn, 1024, K, sbase);
}

// out-projection GEMM + residual
__global__ void __launch_bounds__(256) outproj_gemm_kernel(
    const float* __restrict__ bout, const float* __restrict__ x, float* __restrict__ out) {
    extern __shared__ char smem[];
    uint32_t sbase = smem_u32(smem);
    int bm = blockIdx.y * 128, bn = blockIdx.x * 128;
    gemm_body<1>(g_hnh, g_wo, bout, x, out, nullptr, bm, bn, 1024, 1024, sbase);
}

// ================= FA2-style attention (mma.sync bf16), 256 threads, 128 q-rows =================
__global__ void __launch_bounds__(256) attn_mma_kernel() {
    extern __shared__ char smem[];
    __nv_bfloat16* Ks = (__nv_bfloat16*)smem;          // 256 x 72
    __nv_bfloat16* Vs = Ks + 256 * 72;
    uint32_t sbK = smem_u32(Ks), sbV = smem_u32(Vs);

    int tid = threadIdx.x, w = tid >> 5, lane = tid & 31;
    int b = blockIdx.z, h = blockIdx.y, q0 = blockIdx.x * 128;
    int g = lane >> 2, t4 = lane & 3;

    for (int i = tid; i < 2048; i += 256) {
        int r = i >> 3, q8 = i & 7;
        size_t go = (size_t)(b * 256 + r) * 1024 + h * 64 + q8 * 8;
        *(uint4*)(Ks + r * 72 + q8 * 8) = *(const uint4*)(g_kh + go);
        *(uint4*)(Vs + r * 72 + q8 * 8) = *(const uint4*)(g_vh + go);
    }
    __syncthreads();

    uint32_t aq[4][4];
    const __nv_bfloat16* qb = g_qh + (size_t)(b * 1024 + q0 + w * 16) * 1024 + h * 64;
    #pragma unroll
    for (int ks = 0; ks < 4; ks++) {
        aq[ks][0] = *(const uint32_t*)(qb + (size_t)g * 1024       + ks * 16 + 2 * t4);
        aq[ks][1] = *(const uint32_t*)(qb + (size_t)(g + 8) * 1024 + ks * 16 + 2 * t4);
        aq[ks][2] = *(const uint32_t*)(qb + (size_t)g * 1024       + ks * 16 + 8 + 2 * t4);
        aq[ks][3] = *(const uint32_t*)(qb + (size_t)(g + 8) * 1024 + ks * 16 + 8 + 2 * t4);
    }

    float o[8][4] = {};
    float m0 = -1e30f, m1 = -1e30f, l0 = 0.f, l1 = 0.f;

    uint32_t bRowOff = ((lane >> 4) * 8 + (lane & 7));
    uint32_t bColOff = ((lane >> 3) & 1) * 16;
    uint32_t vRowOff = (((lane >> 3) & 1) * 8 + (lane & 7));
    uint32_t vColOff = (lane >> 4) * 16;

    for (int c = 0; c < 4; c++) {
        int n0 = c * 64;
        float s[8][4] = {};
        #pragma unroll
        for (int ks = 0; ks < 4; ks++) {
            #pragma unroll
            for (int np = 0; np < 4; np++) {
                uint32_t r0, r1, r2, r3;
                uint32_t bd = sbK + (n0 + np * 16 + bRowOff) * 144 + bColOff + ks * 32;
                ldsm_x4(r0, r1, r2, r3, bd);
                uint32_t blo[2] = {r0, r1}, bhi[2] = {r2, r3};
                mma16816(s[np * 2],     aq[ks], blo);
                mma16816(s[np * 2 + 1], aq[ks], bhi);
            }
        }
        float mx0 = -1e30f, mx1 = -1e30f;
        #pragma unroll
        for (int j = 0; j < 8; j++) {
            #pragma unroll
            for (int r = 0; r < 4; r++) s[j][r] *= 0.125f;
            mx0 = fmaxf(mx0, fmaxf(s[j][0], s[j][1]));
            mx1 = fmaxf(mx1, fmaxf(s[j][2], s[j][3]));
        }
        mx0 = fmaxf(mx0, __shfl_xor_sync(0xffffffffu, mx0, 1));
        mx0 = fmaxf(mx0, __shfl_xor_sync(0xffffffffu, mx0, 2));
        mx1 = fmaxf(mx1, __shfl_xor_sync(0xffffffffu, mx1, 1));
        mx1 = fmaxf(mx1, __shfl_xor_sync(0xffffffffu, mx1, 2));
        float nm0 = fmaxf(m0, mx0), nm1 = fmaxf(m1, mx1);
        float al0 = __expf(m0 - nm0), al1 = __expf(m1 - nm1);
        m0 = nm0; m1 = nm1;
        float sum0 = 0.f, sum1 = 0.f;
        #pragma unroll
        for (int j = 0; j < 8; j++) {
            s[j][0] = __expf(s[j][0] - m0);
            s[j][1] = __expf(s[j][1] - m0);
            s[j][2] = __expf(s[j][2] - m1);
            s[j][3] = __expf(s[j][3] - m1);
            sum0 += s[j][0] + s[j][1];
            sum1 += s[j][2] + s[j][3];
        }
        sum0 += __shfl_xor_sync(0xffffffffu, sum0, 1);
        sum0 += __shfl_xor_sync(0xffffffffu, sum0, 2);
        sum1 += __shfl_xor_sync(0xffffffffu, sum1, 1);
        sum1 += __shfl_xor_sync(0xffffffffu, sum1, 2);
        l0 = l0 * al0 + sum0;
        l1 = l1 * al1 + sum1;
        #pragma unroll
        for (int dt = 0; dt < 8; dt++) {
            o[dt][0] *= al0; o[dt][1] *= al0;
            o[dt][2] *= al1; o[dt][3] *= al1;
        }
        uint32_t pa[4][4];
        #pragma unroll
        for (int j = 0; j < 4; j++) {
            pa[j][0] = pack_bf16x2(s[2*j][0],   s[2*j][1]);
            pa[j][1] = pack_bf16x2(s[2*j][2],   s[2*j][3]);
            pa[j][2] = pack_bf16x2(s[2*j+1][0], s[2*j+1][1]);
            pa[j][3] = pack_bf16x2(s[2*j+1][2], s[2*j+1][3]);
        }
        #pragma unroll
        for (int j = 0; j < 4; j++) {
            #pragma unroll
            for (int dp = 0; dp < 4; dp++) {
                uint32_t r0, r1, r2, r3;
                uint32_t vd = sbV + (n0 + j * 16 + vRowOff) * 144 + dp * 32 + vColOff;
                ldsm_x4_t(r0, r1, r2, r3, vd);
                uint32_t blo[2] = {r0, r1}, bhi[2] = {r2, r3};
                mma16816(o[dp * 2],     pa[j], blo);
                mma16816(o[dp * 2 + 1], pa[j], bhi);
            }
        }
    }
    float inv0 = 1.f / l0, inv1 = 1.f / l1;
    float* yb = g_y + (size_t)(b * 1024 + q0 + w * 16) * 1024 + h * 64;
    #pragma unroll
    for (int dt = 0; dt < 8; dt++) {
        int col = dt * 8 + 2 * t4;
        *(float2*)(yb + (size_t)g * 1024 + col)       = make_float2(o[dt][0] * inv0, o[dt][1] * inv0);
        *(float2*)(yb + (size_t)(g + 8) * 1024 + col) = make_float2(o[dt][2] * inv1, o[dt][3] * inv1);
    }
}

// ================= silu(emb) @ Wemb: split-K partials =================
__global__ void __launch_bounds__(128) emb_gemv_splitk(const float* __restrict__ emb,
                                                       const float* __restrict__ Wemb) {
    int j = blockIdx.x * 128 + threadIdx.x;
    int kc = blockIdx.y * 256;
    __shared__ float se[8][256];
    for (int i = threadIdx.x; i < 2048; i += 128) {
        int bb = i >> 8, t = i & 255;
        float e = emb[bb * 2048 + kc + t];
        se[bb][t] = e / (1.f + __expf(-e));
    }
    __syncthreads();
    float acc[8] = {};
    #pragma unroll 4
    for (int t = 0; t < 256; t++) {
        float w = Wemb[(size_t)(kc + t) * 2048 + j];
        #pragma unroll
        for (int bb = 0; bb < 8; bb++) acc[bb] += se[bb][t] * w;
    }
    #pragma unroll
    for (int bb = 0; bb < 8; bb++)
        g_embp[(blockIdx.y * 8 + bb) * 2048 + j] = acc[bb];
}
__global__ void emb_reduce(const float* __restrict__ bemb) {
    int idx = blockIdx.x * 1024 + threadIdx.x;   // 16384 total
    int bb = idx >> 11, j = idx & 2047;
    float s = bemb[j];
    #pragma unroll
    for (int ky = 0; ky < 8; ky++) s += g_embp[(ky * 8 + bb) * 2048 + j];
    g_embo[bb * 2048 + j] = s;
}

// ================= LN(y)*(1+scale)+shift -> silu -> bf16 =================
__global__ void modulate_kernel(const float* __restrict__ gam, const float* __restrict__ bet) {
    int row = blockIdx.x;
    int b = row >> 10;
    const float* yr = g_y + (size_t)row * 1024;
    float sum = 0.f, sq = 0.f;
    for (int i = threadIdx.x; i < 1024; i += blockDim.x) {
        float v = yr[i];
        sum += v; sq += v * v;
    }
    __shared__ float s1[8], s2[8];
    #pragma unroll
    for (int o = 16; o; o >>= 1) {
        sum += __shfl_xor_sync(0xffffffffu, sum, o);
        sq  += __shfl_xor_sync(0xffffffffu, sq,  o);
    }
    int w = threadIdx.x >> 5, l = threadIdx.x & 31;
    if (l == 0) { s1[w] = sum; s2[w] = sq; }
    __syncthreads();
    __shared__ float mean_s, inv_s;
    if (threadIdx.x == 0) {
        float ts = 0.f, tq = 0.f;
        for (int i = 0; i < 8; i++) { ts += s1[i]; tq += s2[i]; }
        float mean = ts * (1.f / 1024.f);
        float var = tq * (1.f / 1024.f) - mean * mean;
        mean_s = mean;
        inv_s = rsqrtf(var + 1e-5f);
    }
    __syncthreads();
    float mean = mean_s, inv = inv_s;
    for (int i = threadIdx.x; i < 1024; i += blockDim.x) {
        float nv = (yr[i] - mean) * inv * gam[i] + bet[i];
        float sc = g_embo[b * 2048 + i];
        float sh = g_embo[b * 2048 + 1024 + i];
        float hv = nv * (1.f + sc) + sh;
        g_hnh[(size_t)row * 1024 + i] = __float2bfloat16(hv / (1.f + __expf(-hv)));
    }
}

// ================= launch =================
extern "C" void kernel_launch(void* const* d_in, const int* in_sizes, int n_in,
                              void* d_out, int out_size) {
    const float* x     = (const float*)d_in[0];
    const float* xf    = (const float*)d_in[1];
    const float* emb   = (const float*)d_in[2];
    const float* ln_g  = (const float*)d_in[3];
    const float* ln_b  = (const float*)d_in[4];
    const float* cln_g = (const float*)d_in[5];
    const float* cln_b = (const float*)d_in[6];
    const float* Wq    = (const float*)d_in[7];
    const float* bq    = (const float*)d_in[8];
    const float* Wk    = (const float*)d_in[9];
    const float* bk    = (const float*)d_in[10];
    const float* Wv    = (const float*)d_in[11];
    const float* bv    = (const float*)d_in[12];
    const float* sln_g = (const float*)d_in[13];
    const float* sln_b = (const float*)d_in[14];
    const float* Wemb  = (const float*)d_in[15];
    const float* bemb  = (const float*)d_in[16];
    const float* Wout  = (const float*)d_in[17];
    const float* bout  = (const float*)d_in[18];
    float* out = (float*)d_out;

    static const int SMEM_ATTN = 2 * 256 * 144;      // 73728
    cudaFuncSetAttribute(qkv_gemm_kernel,     cudaFuncAttributeMaxDynamicSharedMemorySize, GEMM_SMEM);
    cudaFuncSetAttribute(outproj_gemm_kernel, cudaFuncAttributeMaxDynamicSharedMemorySize, GEMM_SMEM);
    cudaFuncSetAttribute(attn_mma_kernel,     cudaFuncAttributeMaxDynamicSharedMemorySize, SMEM_ATTN);

    // 1) LayerNorms -> bf16 (merged)
    ln_all_kernel<<<8192 + 2048, 256>>>(x, ln_g, ln_b, xf, cln_g, cln_b);

    // 2) Weight transposes -> bf16 (merged); emb path is independent, issue here too
    wsplit_all_kernel<<<3584, dim3(32, 8)>>>(Wq, Wk, Wv, Wout);
    emb_gemv_splitk<<<dim3(16, 8), 128>>>(emb, Wemb);
    emb_reduce<<<16, 1024>>>(bemb);

    // 3) q/k/v projections (one launch, 768 tiles)
    qkv_gemm_kernel<<<768, 256, GEMM_SMEM>>>(bq, bk, bv);

    // 4) Attention
    attn_mma_kernel<<<dim3(8, 16, 8), 256, SMEM_ATTN>>>();

    // 5) Modulate
    modulate_kernel<<<8192, 256>>>(sln_g, sln_b);

    // 6) Output projection + residual
    outproj_gemm_kernel<<<dim3(8, 64), 256, GEMM_SMEM>>>(bout, x, out);
}

// round 10
// speedup vs baseline: 6.5835x; 1.5961x over previous
#include <cuda_runtime.h>
#include <cuda_bf16.h>
#include <cstdint>
#include <cstddef>

// Problem constants: B=8, T=1024, D=1024, N=256, L=768, H=16, hd=64, TE=2048

// ================= helpers =================
__device__ __forceinline__ uint32_t smem_u32(const void* p) {
    uint32_t a;
    asm("{ .reg .u64 t; cvta.to.shared.u64 t, %1; cvt.u32.u64 %0, t; }" : "=r"(a) : "l"(p));
    return a;
}
#define CP_ASYNC16(smem, gptr) \
    asm volatile("cp.async.cg.shared.global [%0], [%1], 16;" :: "r"(smem), "l"(gptr))
#define CP_ASYNC_COMMIT() asm volatile("cp.async.commit_group;" ::: "memory")

__device__ __forceinline__ void ldsm_x4(uint32_t& r0, uint32_t& r1, uint32_t& r2, uint32_t& r3,
                                        uint32_t addr) {
    asm volatile("ldmatrix.sync.aligned.m8n8.x4.shared.b16 {%0,%1,%2,%3}, [%4];"
                 : "=r"(r0), "=r"(r1), "=r"(r2), "=r"(r3) : "r"(addr));
}
__device__ __forceinline__ void ldsm_x4_t(uint32_t& r0, uint32_t& r1, uint32_t& r2, uint32_t& r3,
                                          uint32_t addr) {
    asm volatile("ldmatrix.sync.aligned.m8n8.x4.trans.shared.b16 {%0,%1,%2,%3}, [%4];"
                 : "=r"(r0), "=r"(r1), "=r"(r2), "=r"(r3) : "r"(addr));
}
__device__ __forceinline__ void mma16816(float* d, const uint32_t* a, const uint32_t* b) {
    asm volatile("mma.sync.aligned.m16n8k16.row.col.f32.bf16.bf16.f32 "
                 "{%0,%1,%2,%3}, {%4,%5,%6,%7}, {%8,%9}, {%0,%1,%2,%3};"
                 : "+f"(d[0]), "+f"(d[1]), "+f"(d[2]), "+f"(d[3])
                 : "r"(a[0]), "r"(a[1]), "r"(a[2]), "r"(a[3]), "r"(b[0]), "r"(b[1]));
}
__device__ __forceinline__ uint32_t pack_bf16x2(float a, float b) {
    __nv_bfloat162 h = __floats2bfloat162_rn(a, b);
    return *(uint32_t*)&h;
}

// ================= scratch (device globals) =================
__device__ float g_embo[8u*2048u];
__device__ float g_embp[8u*8u*2048u];          // split-K partials [ky][b][j]
__device__ __nv_bfloat16 g_yh [8192u*1024u];   // attn out bf16
__device__ __nv_bfloat16 g_xnh[8192u*1024u];   // LN(x) bf16
__device__ __nv_bfloat16 g_xfh[2048u*768u];    // LN(xf) bf16
__device__ __nv_bfloat16 g_qh [8192u*1024u];
__device__ __nv_bfloat16 g_kh [2048u*1024u];
__device__ __nv_bfloat16 g_vh [2048u*1024u];
__device__ __nv_bfloat16 g_hnh[8192u*1024u];
__device__ __nv_bfloat16 g_wq [1024u*1024u];   // W^T bf16 [N,K]
__device__ __nv_bfloat16 g_wk [1024u*768u];
__device__ __nv_bfloat16 g_wv [1024u*768u];
__device__ __nv_bfloat16 g_wo [1024u*1024u];

// ================= fused preprocess: LN(x), LN(xf), 4x weight transpose, emb split-K =================
// grid: [0,10240) LN rows, [10240,13824) wsplit tiles, [13824,13888) emb split-K blocks. 256 thr.
__global__ void __launch_bounds__(256) preprocess_kernel(
    const float* __restrict__ x,  const float* __restrict__ ln_g, const float* __restrict__ ln_b,
    const float* __restrict__ xf, const float* __restrict__ cg,   const float* __restrict__ cb,
    const float* __restrict__ Wq, const float* __restrict__ Wk,
    const float* __restrict__ Wv, const float* __restrict__ Wo,
    const float* __restrict__ emb, const float* __restrict__ Wemb) {
    __shared__ float sh[2200];
    int blk = blockIdx.x;
    int tid = threadIdx.x;

    if (blk < 10240) {
        // ---------- LayerNorm ----------
        int row = blk;
        const float* X; const float* gam; const float* bet; __nv_bfloat16* O; int nj, Wd;
        if (row < 8192) { X = x; gam = ln_g; bet = ln_b; O = g_xnh; Wd = 1024; nj = 4; }
        else { row -= 8192; X = xf; gam = cg; bet = cb; O = g_xfh; Wd = 768; nj = 3; }
        const float* xr = X + (size_t)row * Wd;
        float vc[4];
        float sum = 0.f, sq = 0.f;
        for (int j = 0; j < nj; j++) {
            float v = xr[tid + j * 256];
            vc[j] = v;
            sum += v; sq += v * v;
        }
        #pragma unroll
        for (int o = 16; o; o >>= 1) {
            sum += __shfl_xor_sync(0xffffffffu, sum, o);
            sq  += __shfl_xor_sync(0xffffffffu, sq,  o);
        }
        int w = tid >> 5, l = tid & 31;
        if (l == 0) { sh[w] = sum; sh[8 + w] = sq; }
        __syncthreads();
        if (tid == 0) {
            float ts = 0.f, tq = 0.f;
            for (int i = 0; i < 8; i++) { ts += sh[i]; tq += sh[8 + i]; }
            float mean = ts / Wd;
            float var = tq / Wd - mean * mean;
            sh[16] = mean;
            sh[17] = rsqrtf(var + 1e-5f);
        }
        __syncthreads();
        float mean = sh[16], inv = sh[17];
        for (int j = 0; j < nj; j++) {
            int i = tid + j * 256;
            O[(size_t)row * Wd + i] = __float2bfloat16((vc[j] - mean) * inv * gam[i] + bet[i]);
        }
    } else if (blk < 13824) {
        // ---------- weight transpose W[K,N] -> T[N,K] bf16 ----------
        int idx = blk - 10240;
        const float* W; __nv_bfloat16* Th; int K, kt;
        if (idx < 1024)      { W = Wq; Th = g_wq; K = 1024; kt = 32; }
        else if (idx < 1792) { W = Wk; Th = g_wk; K = 768;  kt = 24; idx -= 1024; }
        else if (idx < 2560) { W = Wv; Th = g_wv; K = 768;  kt = 24; idx -= 1792; }
        else                 { W = Wo; Th = g_wo; K = 1024; kt = 32; idx -= 2560; }
        int k0 = (idx % kt) * 32, n0 = (idx / kt) * 32;
        float (*t)[33] = (float(*)[33])sh;
        int tx = tid & 31, ty = tid >> 5;
        #pragma unroll
        for (int r = ty; r < 32; r += 8)
            t[r][tx] = W[(size_t)(k0 + r) * 1024 + n0 + tx];
        __syncthreads();
        #pragma unroll
        for (int r = ty; r < 32; r += 8)
            Th[(size_t)(n0 + r) * K + k0 + tx] = __float2bfloat16(t[tx][r]);
    } else {
        // ---------- silu(emb) @ Wemb split-K partials ----------
        int idx = blk - 13824;            // 64 blocks: kcblk [0,8) x jblk [0,8)
        int kc = (idx >> 3) * 256;
        int j = (idx & 7) * 256 + tid;
        float (*se)[256] = (float(*)[256])sh;
        for (int i = tid; i < 2048; i += 256) {
            int bb = i >> 8, t = i & 255;
            float e = emb[bb * 2048 + kc + t];
            se[bb][t] = e / (1.f + __expf(-e));
        }
        __syncthreads();
        float acc[8] = {};
        #pragma unroll 4
        for (int t = 0; t < 256; t++) {
            float wv = Wemb[(size_t)(kc + t) * 2048 + j];
            #pragma unroll
            for (int bb = 0; bb < 8; bb++) acc[bb] += se[bb][t] * wv;
        }
        #pragma unroll
        for (int bb = 0; bb < 8; bb++)
            g_embp[((idx >> 3) * 8 + bb) * 2048 + j] = acc[bb];
    }
}

// ================= mma.sync bf16 GEMM body (3-stage cp.async, 1 sync/chunk) =================
static constexpr uint32_t TSTRIDE = 80;            // 32 bf16 + 8 pad bytes
static constexpr uint32_t TILE_B  = 128 * TSTRIDE; // 10240
static constexpr uint32_t STAGE_B = 2 * TILE_B;    // 20480 (A, B)
static constexpr int GEMM_SMEM = 3 * (int)STAGE_B; // 61440

// MODE: 1 = f32 out + residual, 2 = bf16 out
template<int MODE>
__device__ __forceinline__ void gemm_body(
    const __nv_bfloat16* __restrict__ A, const __nv_bfloat16* __restrict__ Bw,
    const float* __restrict__ bias, const float* __restrict__ R,
    float* __restrict__ Cf, __nv_bfloat16* __restrict__ Cb,
    int bm, int bn, int Nn, int K, uint32_t sbase) {
    int tid = threadIdx.x, wid = tid >> 5, lane = tid & 31;
    int wm = wid >> 2, wn = wid & 3;

    const __nv_bfloat16* gA = A  + (size_t)bm * K;
    const __nv_bfloat16* gB = Bw + (size_t)bn * K;

    float acc[4][4][4] = {};
    const int NC = K >> 5;

    auto load_stage = [&](int c) {
        uint32_t sb = sbase + (uint32_t)(c % 3) * STAGE_B;
        int kc = c * 32;
        #pragma unroll
        for (int i = tid; i < 512; i += 256) {
            int r = i >> 2, q = i & 3;
            CP_ASYNC16(sb + r * TSTRIDE + q * 16,          gA + (size_t)r * K + kc + q * 8);
            CP_ASYNC16(sb + TILE_B + r * TSTRIDE + q * 16, gB + (size_t)r * K + kc + q * 8);
        }
    };

    load_stage(0); CP_ASYNC_COMMIT();
    load_stage(1); CP_ASYNC_COMMIT();

    uint32_t aRow = (uint32_t)(wm * 64) + ((lane >> 3) & 1) * 8 + (lane & 7);
    uint32_t aCol = (lane >> 4) * 16;
    uint32_t bRow = (uint32_t)(wn * 32) + ((lane >> 4) * 8) + (lane & 7);
    uint32_t bCol = ((lane >> 3) & 1) * 16;

    for (int c = 0; c < NC; c++) {
        asm volatile("cp.async.wait_group 1;" ::: "memory");
        __syncthreads();
        if (c + 2 < NC) load_stage(c + 2);
        CP_ASYNC_COMMIT();

        uint32_t sb = sbase + (uint32_t)(c % 3) * STAGE_B;
        #pragma unroll
        for (int kk = 0; kk < 2; kk++) {
            uint32_t kOff = kk * 32;
            uint32_t ah[4][4], bh[4][2];
            #pragma unroll
            for (int mt = 0; mt < 4; mt++) {
                uint32_t ad = sb + (aRow + mt * 16) * TSTRIDE + aCol + kOff;
                ldsm_x4(ah[mt][0], ah[mt][1], ah[mt][2], ah[mt][3], ad);
            }
            #pragma unroll
            for (int np = 0; np < 2; np++) {
                uint32_t bd = sb + TILE_B + (bRow + np * 16) * TSTRIDE + bCol + kOff;
                ldsm_x4(bh[np*2][0], bh[np*2][1], bh[np*2+1][0], bh[np*2+1][1], bd);
            }
            #pragma unroll
            for (int mt = 0; mt < 4; mt++)
                #pragma unroll
                for (int nt = 0; nt < 4; nt++)
                    mma16816(acc[mt][nt], ah[mt], bh[nt]);
        }
    }

    int g = lane >> 2, tg = lane & 3;
    #pragma unroll
    for (int mt = 0; mt < 4; mt++) {
        int r0 = bm + wm * 64 + mt * 16 + g;
        #pragma unroll
        for (int nt = 0; nt < 4; nt++) {
            int col = bn + wn * 32 + nt * 8 + tg * 2;
            float b0 = bias[col], b1 = bias[col + 1];
            size_t o0 = (size_t)r0 * Nn + col;
            size_t o1 = (size_t)(r0 + 8) * Nn + col;
            float v00 = acc[mt][nt][0] + b0, v01 = acc[mt][nt][1] + b1;
            float v10 = acc[mt][nt][2] + b0, v11 = acc[mt][nt][3] + b1;
            if (MODE == 2) {
                *(uint32_t*)&Cb[o0] = pack_bf16x2(v00, v01);
                *(uint32_t*)&Cb[o1] = pack_bf16x2(v10, v11);
            } else {
                float2 r00 = *(const float2*)&R[o0];
                float2 r11 = *(const float2*)&R[o1];
                *(float2*)&Cf[o0] = make_float2(v00 + r00.x, v01 + r00.y);
                *(float2*)&Cf[o1] = make_float2(v10 + r11.x, v11 + r11.y);
            }
        }
    }
}

// merged q/k/v projection GEMM (768 tiles) + emb reduce (16 tiles)
__global__ void __launch_bounds__(256) qkv_gemm_kernel(
    const float* __restrict__ bq, const float* __restrict__ bk, const float* __restrict__ bv,
    const float* __restrict__ bemb) {
    extern __shared__ char smem[];
    uint32_t sbase = smem_u32(smem);
    int tile = blockIdx.x;
    if (tile >= 768) {
        // emb reduce: 16 blocks x 256 threads x 4 = 16384 elems
        int base = (tile - 768) * 1024;
        for (int j4 = 0; j4 < 4; j4++) {
            int idx = base + threadIdx.x + j4 * 256;
            int bb = idx >> 11, j = idx & 2047;
            float s = bemb[j];
            #pragma unroll
            for (int ky = 0; ky < 8; ky++) s += g_embp[(ky * 8 + bb) * 2048 + j];
            g_embo[bb * 2048 + j] = s;
        }
        return;
    }
    const __nv_bfloat16 *A, *Bw; const float* bias; __nv_bfloat16* Cb; int K;
    int bm, bn;
    if (tile < 512) {            // Q: 64 x 8 tiles
        A = g_xnh; Bw = g_wq; bias = bq; Cb = g_qh; K = 1024;
        bm = (tile >> 3) * 128; bn = (tile & 7) * 128;
    } else if (tile < 640) {     // K
        tile -= 512;
        A = g_xfh; Bw = g_wk; bias = bk; Cb = g_kh; K = 768;
        bm = (tile >> 3) * 128; bn = (tile & 7) * 128;
    } else {                     // V
        tile -= 640;
        A = g_xfh; Bw = g_wv; bias = bv; Cb = g_vh; K = 768;
        bm = (tile >> 3) * 128; bn = (tile & 7) * 128;
    }
    gemm_body<2>(A, Bw, bias, nullptr, nullptr, Cb, bm, bn, 1024, K, sbase);
}

// out-projection GEMM + residual
__global__ void __launch_bounds__(256) outproj_gemm_kernel(
    const float* __restrict__ bout, const float* __restrict__ x, float* __restrict__ out) {
    extern __shared__ char smem[];
    uint32_t sbase = smem_u32(smem);
    gemm_body<1>(g_hnh, g_wo, bout, x, out, nullptr, blockIdx.y * 128, blockIdx.x * 128,
                 1024, 1024, sbase);
}

// ================= FA2-style attention (mma.sync bf16), 256 threads, 128 q-rows =================
__global__ void __launch_bounds__(256) attn_mma_kernel() {
    extern __shared__ char smem[];
    __nv_bfloat16* Ks = (__nv_bfloat16*)smem;          // 256 x 72
    __nv_bfloat16* Vs = Ks + 256 * 72;
    uint32_t sbK = smem_u32(Ks), sbV = smem_u32(Vs);

    int tid = threadIdx.x, w = tid >> 5, lane = tid & 31;
    int b = blockIdx.z, h = blockIdx.y, q0 = blockIdx.x * 128;
    int g = lane >> 2, t4 = lane & 3;
    const float SC = 0.125f * 1.44269504f;   // log2-domain scores

    for (int i = tid; i < 2048; i += 256) {
        int r = i >> 3, q8 = i & 7;
        size_t go = (size_t)(b * 256 + r) * 1024 + h * 64 + q8 * 8;
        *(uint4*)(Ks + r * 72 + q8 * 8) = *(const uint4*)(g_kh + go);
        *(uint4*)(Vs + r * 72 + q8 * 8) = *(const uint4*)(g_vh + go);
    }
    __syncthreads();

    uint32_t aq[4][4];
    const __nv_bfloat16* qb = g_qh + (size_t)(b * 1024 + q0 + w * 16) * 1024 + h * 64;
    #pragma unroll
    for (int ks = 0; ks < 4; ks++) {
        aq[ks][0] = *(const uint32_t*)(qb + (size_t)g * 1024       + ks * 16 + 2 * t4);
        aq[ks][1] = *(const uint32_t*)(qb + (size_t)(g + 8) * 1024 + ks * 16 + 2 * t4);
        aq[ks][2] = *(const uint32_t*)(qb + (size_t)g * 1024       + ks * 16 + 8 + 2 * t4);
        aq[ks][3] = *(const uint32_t*)(qb + (size_t)(g + 8) * 1024 + ks * 16 + 8 + 2 * t4);
    }

    float o[8][4] = {};
    float m0 = -1e30f, m1 = -1e30f, l0 = 0.f, l1 = 0.f;

    uint32_t bRowOff = ((lane >> 4) * 8 + (lane & 7));
    uint32_t bColOff = ((lane >> 3) & 1) * 16;
    uint32_t vRowOff = (((lane >> 3) & 1) * 8 + (lane & 7));
    uint32_t vColOff = (lane >> 4) * 16;

    for (int c = 0; c < 4; c++) {
        int n0 = c * 64;
        float s[8][4] = {};
        #pragma unroll
        for (int ks = 0; ks < 4; ks++) {
            #pragma unroll
            for (int np = 0; np < 4; np++) {
                uint32_t r0, r1, r2, r3;
                uint32_t bd = sbK + (n0 + np * 16 + bRowOff) * 144 + bColOff + ks * 32;
                ldsm_x4(r0, r1, r2, r3, bd);
                uint32_t blo[2] = {r0, r1}, bhi[2] = {r2, r3};
                mma16816(s[np * 2],     aq[ks], blo);
                mma16816(s[np * 2 + 1], aq[ks], bhi);
            }
        }
        float mx0 = -1e30f, mx1 = -1e30f;
        #pragma unroll
        for (int j = 0; j < 8; j++) {
            #pragma unroll
            for (int r = 0; r < 4; r++) s[j][r] *= SC;
            mx0 = fmaxf(mx0, fmaxf(s[j][0], s[j][1]));
            mx1 = fmaxf(mx1, fmaxf(s[j][2], s[j][3]));
        }
        mx0 = fmaxf(mx0, __shfl_xor_sync(0xffffffffu, mx0, 1));
        mx0 = fmaxf(mx0, __shfl_xor_sync(0xffffffffu, mx0, 2));
        mx1 = fmaxf(mx1, __shfl_xor_sync(0xffffffffu, mx1, 1));
        mx1 = fmaxf(mx1, __shfl_xor_sync(0xffffffffu, mx1, 2));
        float nm0 = fmaxf(m0, mx0), nm1 = fmaxf(m1, mx1);
        float al0 = exp2f(m0 - nm0), al1 = exp2f(m1 - nm1);
        m0 = nm0; m1 = nm1;
        float sum0 = 0.f, sum1 = 0.f;
        #pragma unroll
        for (int j = 0; j < 8; j++) {
            s[j][0] = exp2f(s[j][0] - m0);
            s[j][1] = exp2f(s[j][1] - m0);
            s[j][2] = exp2f(s[j][2] - m1);
            s[j][3] = exp2f(s[j][3] - m1);
            sum0 += s[j][0] + s[j][1];
            sum1 += s[j][2] + s[j][3];
        }
        sum0 += __shfl_xor_sync(0xffffffffu, sum0, 1);
        sum0 += __shfl_xor_sync(0xffffffffu, sum0, 2);
        sum1 += __shfl_xor_sync(0xffffffffu, sum1, 1);
        sum1 += __shfl_xor_sync(0xffffffffu, sum1, 2);
        l0 = l0 * al0 + sum0;
        l1 = l1 * al1 + sum1;
        #pragma unroll
        for (int dt = 0; dt < 8; dt++) {
            o[dt][0] *= al0; o[dt][1] *= al0;
            o[dt][2] *= al1; o[dt][3] *= al1;
        }
        uint32_t pa[4][4];
        #pragma unroll
        for (int j = 0; j < 4; j++) {
            pa[j][0] = pack_bf16x2(s[2*j][0],   s[2*j][1]);
            pa[j][1] = pack_bf16x2(s[2*j][2],   s[2*j][3]);
            pa[j][2] = pack_bf16x2(s[2*j+1][0], s[2*j+1][1]);
            pa[j][3] = pack_bf16x2(s[2*j+1][2], s[2*j+1][3]);
        }
        #pragma unroll
        for (int j = 0; j < 4; j++) {
            #pragma unroll
            for (int dp = 0; dp < 4; dp++) {
                uint32_t r0, r1, r2, r3;
                uint32_t vd = sbV + (n0 + j * 16 + vRowOff) * 144 + dp * 32 + vColOff;
                ldsm_x4_t(r0, r1, r2, r3, vd);
                uint32_t blo[2] = {r0, r1}, bhi[2] = {r2, r3};
                mma16816(o[dp * 2],     pa[j], blo);
                mma16816(o[dp * 2 + 1], pa[j], bhi);
            }
        }
    }
    float inv0 = 1.f / l0, inv1 = 1.f / l1;
    __nv_bfloat16* yb = g_yh + (size_t)(b * 1024 + q0 + w * 16) * 1024 + h * 64;
    #pragma unroll
    for (int dt = 0; dt < 8; dt++) {
        int col = dt * 8 + 2 * t4;
        *(uint32_t*)(yb + (size_t)g * 1024 + col)       = pack_bf16x2(o[dt][0] * inv0, o[dt][1] * inv0);
        *(uint32_t*)(yb + (size_t)(g + 8) * 1024 + col) = pack_bf16x2(o[dt][2] * inv1, o[dt][3] * inv1);
    }
}

// ================= LN(y)*(1+scale)+shift -> silu -> bf16 (single pass, y in bf16) =================
__global__ void __launch_bounds__(256) modulate_kernel(const float* __restrict__ gam,
                                                       const float* __restrict__ bet) {
    int row = blockIdx.x;
    int b = row >> 10;
    const __nv_bfloat16* yr = g_yh + (size_t)row * 1024;
    float vc[4];
    float sum = 0.f, sq = 0.f;
    #pragma unroll
    for (int j = 0; j < 4; j++) {
        float v = __bfloat162float(yr[threadIdx.x + j * 256]);
        vc[j] = v;
        sum += v; sq += v * v;
    }
    __shared__ float s1[8], s2[8];
    #pragma unroll
    for (int o = 16; o; o >>= 1) {
        sum += __shfl_xor_sync(0xffffffffu, sum, o);
        sq  += __shfl_xor_sync(0xffffffffu, sq,  o);
    }
    int w = threadIdx.x >> 5, l = threadIdx.x & 31;
    if (l == 0) { s1[w] = sum; s2[w] = sq; }
    __syncthreads();
    __shared__ float mean_s, inv_s;
    if (threadIdx.x == 0) {
        float ts = 0.f, tq = 0.f;
        for (int i = 0; i < 8; i++) { ts += s1[i]; tq += s2[i]; }
        float mean = ts * (1.f / 1024.f);
        float var = tq * (1.f / 1024.f) - mean * mean;
        mean_s = mean;
        inv_s = rsqrtf(var + 1e-5f);
    }
    __syncthreads();
    float mean = mean_s, inv = inv_s;
    #pragma unroll
    for (int j = 0; j < 4; j++) {
        int i = threadIdx.x + j * 256;
        float nv = (vc[j] - mean) * inv * gam[i] + bet[i];
        float sc = g_embo[b * 2048 + i];
        float sh = g_embo[b * 2048 + 1024 + i];
        float hv = nv * (1.f + sc) + sh;
        g_hnh[(size_t)row * 1024 + i] = __float2bfloat16(hv / (1.f + __expf(-hv)));
    }
}

// ================= launch =================
extern "C" void kernel_launch(void* const* d_in, const int* in_sizes, int n_in,
                              void* d_out, int out_size) {
    const float* x     = (const float*)d_in[0];
    const float* xf    = (const float*)d_in[1];
    const float* emb   = (const float*)d_in[2];
    const float* ln_g  = (const float*)d_in[3];
    const float* ln_b  = (const float*)d_in[4];
    const float* cln_g = (const float*)d_in[5];
    const float* cln_b = (const float*)d_in[6];
    const float* Wq    = (const float*)d_in[7];
    const float* bq    = (const float*)d_in[8];
    const float* Wk    = (const float*)d_in[9];
    const float* bk    = (const float*)d_in[10];
    const float* Wv    = (const float*)d_in[11];
    const float* bv    = (const float*)d_in[12];
    const float* sln_g = (const float*)d_in[13];
    const float* sln_b = (const float*)d_in[14];
    const float* Wemb  = (const float*)d_in[15];
    const float* bemb  = (const float*)d_in[16];
    const float* Wout  = (const float*)d_in[17];
    const float* bout  = (const float*)d_in[18];
    float* out = (float*)d_out;

    static const int SMEM_ATTN = 2 * 256 * 144;      // 73728
    cudaFuncSetAttribute(qkv_gemm_kernel,     cudaFuncAttributeMaxDynamicSharedMemorySize, GEMM_SMEM);
    cudaFuncSetAttribute(outproj_gemm_kernel, cudaFuncAttributeMaxDynamicSharedMemorySize, GEMM_SMEM);
    cudaFuncSetAttribute(attn_mma_kernel,     cudaFuncAttributeMaxDynamicSharedMemorySize, SMEM_ATTN);

    // 1) preprocess: LN(x), LN(xf), weight transposes, emb split-K partials
    preprocess_kernel<<<13888, 256>>>(x, ln_g, ln_b, xf, cln_g, cln_b,
                                      Wq, Wk, Wv, Wout, emb, Wemb);

    // 2) q/k/v projections + emb reduce
    qkv_gemm_kernel<<<784, 256, GEMM_SMEM>>>(bq, bk, bv, bemb);

    // 3) attention
    attn_mma_kernel<<<dim3(8, 16, 8), 256, SMEM_ATTN>>>();

    // 4) modulate
    modulate_kernel<<<8192, 256>>>(sln_g, sln_b);

    // 5) output projection + residual
    outproj_gemm_kernel<<<dim3(8, 64), 256, GEMM_SMEM>>>(bout, x, out);
}

// round 11
// speedup vs baseline: 6.6430x; 1.0090x over previous
#include <cuda_runtime.h>
#include <cuda_bf16.h>
#include <cstdint>
#include <cstddef>

// Problem constants: B=8, T=1024, D=1024, N=256, L=768, H=16, hd=64, TE=2048

// ================= helpers =================
__device__ __forceinline__ uint32_t smem_u32(const void* p) {
    uint32_t a;
    asm("{ .reg .u64 t; cvta.to.shared.u64 t, %1; cvt.u32.u64 %0, t; }" : "=r"(a) : "l"(p));
    return a;
}
#define CP_ASYNC16(smem, gptr) \
    asm volatile("cp.async.cg.shared.global [%0], [%1], 16;" :: "r"(smem), "l"(gptr))
#define CP_ASYNC_COMMIT() asm volatile("cp.async.commit_group;" ::: "memory")

__device__ __forceinline__ void ldsm_x4(uint32_t& r0, uint32_t& r1, uint32_t& r2, uint32_t& r3,
                                        uint32_t addr) {
    asm volatile("ldmatrix.sync.aligned.m8n8.x4.shared.b16 {%0,%1,%2,%3}, [%4];"
                 : "=r"(r0), "=r"(r1), "=r"(r2), "=r"(r3) : "r"(addr));
}
__device__ __forceinline__ void ldsm_x4_t(uint32_t& r0, uint32_t& r1, uint32_t& r2, uint32_t& r3,
                                          uint32_t addr) {
    asm volatile("ldmatrix.sync.aligned.m8n8.x4.trans.shared.b16 {%0,%1,%2,%3}, [%4];"
                 : "=r"(r0), "=r"(r1), "=r"(r2), "=r"(r3) : "r"(addr));
}
__device__ __forceinline__ void mma16816(float* d, const uint32_t* a, const uint32_t* b) {
    asm volatile("mma.sync.aligned.m16n8k16.row.col.f32.bf16.bf16.f32 "
                 "{%0,%1,%2,%3}, {%4,%5,%6,%7}, {%8,%9}, {%0,%1,%2,%3};"
                 : "+f"(d[0]), "+f"(d[1]), "+f"(d[2]), "+f"(d[3])
                 : "r"(a[0]), "r"(a[1]), "r"(a[2]), "r"(a[3]), "r"(b[0]), "r"(b[1]));
}
__device__ __forceinline__ uint32_t pack_bf16x2(float a, float b) {
    __nv_bfloat162 h = __floats2bfloat162_rn(a, b);
    return *(uint32_t*)&h;
}

// ================= scratch (device globals) =================
__device__ float g_embo[8u*2048u];
__device__ float g_embp[8u*8u*2048u];          // split-K partials [ky][b][j]
__device__ __nv_bfloat16 g_yh [8192u*1024u];   // attn out bf16
__device__ __nv_bfloat16 g_xnh[8192u*1024u];   // LN(x) bf16
__device__ __nv_bfloat16 g_xfh[2048u*768u];    // LN(xf) bf16
__device__ __nv_bfloat16 g_qh [8192u*1024u];
__device__ __nv_bfloat16 g_kh [2048u*1024u];
__device__ __nv_bfloat16 g_vh [2048u*1024u];
__device__ __nv_bfloat16 g_hnh[8192u*1024u];
__device__ __nv_bfloat16 g_wq [1024u*1024u];   // W^T bf16 [N,K]
__device__ __nv_bfloat16 g_wk [1024u*768u];
__device__ __nv_bfloat16 g_wv [1024u*768u];
__device__ __nv_bfloat16 g_wo [1024u*1024u];

// ================= fused preprocess: LN(x), LN(xf), 4x weight transpose, emb split-K =================
// grid: [0,10240) LN rows, [10240,13824) wsplit tiles, [13824,13888) emb split-K blocks. 256 thr.
__global__ void __launch_bounds__(256) preprocess_kernel(
    const float* __restrict__ x,  const float* __restrict__ ln_g, const float* __restrict__ ln_b,
    const float* __restrict__ xf, const float* __restrict__ cg,   const float* __restrict__ cb,
    const float* __restrict__ Wq, const float* __restrict__ Wk,
    const float* __restrict__ Wv, const float* __restrict__ Wo,
    const float* __restrict__ emb, const float* __restrict__ Wemb) {
    __shared__ float sh[2200];
    int blk = blockIdx.x;
    int tid = threadIdx.x;

    if (blk < 10240) {
        // ---------- LayerNorm (vectorized: 4 contiguous elems/thread) ----------
        int row = blk;
        const float* X; const float* gam; const float* bet; __nv_bfloat16* O; int Wd;
        if (row < 8192) { X = x; gam = ln_g; bet = ln_b; O = g_xnh; Wd = 1024; }
        else { row -= 8192; X = xf; gam = cg; bet = cb; O = g_xfh; Wd = 768; }
        const float* xr = X + (size_t)row * Wd;
        int i0 = tid * 4;
        bool act = i0 < Wd;
        float4 v4 = act ? *(const float4*)(xr + i0) : make_float4(0.f, 0.f, 0.f, 0.f);
        float sum = v4.x + v4.y + v4.z + v4.w;
        float sq  = v4.x * v4.x + v4.y * v4.y + v4.z * v4.z + v4.w * v4.w;
        #pragma unroll
        for (int o = 16; o; o >>= 1) {
            sum += __shfl_xor_sync(0xffffffffu, sum, o);
            sq  += __shfl_xor_sync(0xffffffffu, sq,  o);
        }
        int w = tid >> 5, l = tid & 31;
        if (l == 0) { sh[w] = sum; sh[8 + w] = sq; }
        __syncthreads();
        if (tid == 0) {
            float ts = 0.f, tq = 0.f;
            for (int i = 0; i < 8; i++) { ts += sh[i]; tq += sh[8 + i]; }
            float mean = ts / Wd;
            float var = tq / Wd - mean * mean;
            sh[16] = mean;
            sh[17] = rsqrtf(var + 1e-5f);
        }
        __syncthreads();
        if (act) {
            float mean = sh[16], inv = sh[17];
            float4 gg = *(const float4*)(gam + i0);
            float4 bb = *(const float4*)(bet + i0);
            uint2 o2;
            o2.x = pack_bf16x2((v4.x - mean) * inv * gg.x + bb.x,
                               (v4.y - mean) * inv * gg.y + bb.y);
            o2.y = pack_bf16x2((v4.z - mean) * inv * gg.z + bb.z,
                               (v4.w - mean) * inv * gg.w + bb.w);
            *(uint2*)(O + (size_t)row * Wd + i0) = o2;
        }
    } else if (blk < 13824) {
        // ---------- weight transpose W[K,N] -> T[N,K] bf16 ----------
        int idx = blk - 10240;
        const float* W; __nv_bfloat16* Th; int K, kt;
        if (idx < 1024)      { W = Wq; Th = g_wq; K = 1024; kt = 32; }
        else if (idx < 1792) { W = Wk; Th = g_wk; K = 768;  kt = 24; idx -= 1024; }
        else if (idx < 2560) { W = Wv; Th = g_wv; K = 768;  kt = 24; idx -= 1792; }
        else                 { W = Wo; Th = g_wo; K = 1024; kt = 32; idx -= 2560; }
        int k0 = (idx % kt) * 32, n0 = (idx / kt) * 32;
        float (*t)[33] = (float(*)[33])sh;
        int tx = tid & 31, ty = tid >> 5;
        #pragma unroll
        for (int r = ty; r < 32; r += 8)
            t[r][tx] = W[(size_t)(k0 + r) * 1024 + n0 + tx];
        __syncthreads();
        #pragma unroll
        for (int r = ty; r < 32; r += 8)
            Th[(size_t)(n0 + r) * K + k0 + tx] = __float2bfloat16(t[tx][r]);
    } else {
        // ---------- silu(emb) @ Wemb split-K partials ----------
        int idx = blk - 13824;            // 64 blocks: kcblk [0,8) x jblk [0,8)
        int kc = (idx >> 3) * 256;
        int j = (idx & 7) * 256 + tid;
        float (*se)[256] = (float(*)[256])sh;
        for (int i = tid; i < 2048; i += 256) {
            int bb = i >> 8, t = i & 255;
            float e = emb[bb * 2048 + kc + t];
            se[bb][t] = e / (1.f + __expf(-e));
        }
        __syncthreads();
        float acc[8] = {};
        #pragma unroll 4
        for (int t = 0; t < 256; t++) {
            float wv = Wemb[(size_t)(kc + t) * 2048 + j];
            #pragma unroll
            for (int bb = 0; bb < 8; bb++) acc[bb] += se[bb][t] * wv;
        }
        #pragma unroll
        for (int bb = 0; bb < 8; bb++)
            g_embp[((idx >> 3) * 8 + bb) * 2048 + j] = acc[bb];
    }
}

// ================= mma.sync bf16 GEMM body (4-stage cp.async, 1 sync/chunk) =================
static constexpr uint32_t TSTRIDE = 80;            // 32 bf16 + 8 pad bytes
static constexpr uint32_t TILE_B  = 128 * TSTRIDE; // 10240
static constexpr uint32_t STAGE_B = 2 * TILE_B;    // 20480 (A, B)
static constexpr int GEMM_SMEM = 4 * (int)STAGE_B; // 81920

// MODE: 1 = f32 out + residual, 2 = bf16 out
template<int MODE>
__device__ __forceinline__ void gemm_body(
    const __nv_bfloat16* __restrict__ A, const __nv_bfloat16* __restrict__ Bw,
    const float* __restrict__ bias, const float* __restrict__ R,
    float* __restrict__ Cf, __nv_bfloat16* __restrict__ Cb,
    int bm, int bn, int Nn, int K, uint32_t sbase) {
    int tid = threadIdx.x, wid = tid >> 5, lane = tid & 31;
    int wm = wid >> 2, wn = wid & 3;

    const __nv_bfloat16* gA = A  + (size_t)bm * K;
    const __nv_bfloat16* gB = Bw + (size_t)bn * K;

    float acc[4][4][4] = {};
    const int NC = K >> 5;

    auto load_stage = [&](int c) {
        uint32_t sb = sbase + (uint32_t)(c & 3) * STAGE_B;
        int kc = c * 32;
        #pragma unroll
        for (int i = tid; i < 512; i += 256) {
            int r = i >> 2, q = i & 3;
            CP_ASYNC16(sb + r * TSTRIDE + q * 16,          gA + (size_t)r * K + kc + q * 8);
            CP_ASYNC16(sb + TILE_B + r * TSTRIDE + q * 16, gB + (size_t)r * K + kc + q * 8);
        }
    };

    load_stage(0); CP_ASYNC_COMMIT();
    load_stage(1); CP_ASYNC_COMMIT();
    load_stage(2); CP_ASYNC_COMMIT();

    uint32_t aRow = (uint32_t)(wm * 64) + ((lane >> 3) & 1) * 8 + (lane & 7);
    uint32_t aCol = (lane >> 4) * 16;
    uint32_t bRow = (uint32_t)(wn * 32) + ((lane >> 4) * 8) + (lane & 7);
    uint32_t bCol = ((lane >> 3) & 1) * 16;

    for (int c = 0; c < NC; c++) {
        asm volatile("cp.async.wait_group 2;" ::: "memory");
        __syncthreads();
        if (c + 3 < NC) load_stage(c + 3);
        CP_ASYNC_COMMIT();

        uint32_t sb = sbase + (uint32_t)(c & 3) * STAGE_B;
        #pragma unroll
        for (int kk = 0; kk < 2; kk++) {
            uint32_t kOff = kk * 32;
            uint32_t ah[4][4], bh[4][2];
            #pragma unroll
            for (int mt = 0; mt < 4; mt++) {
                uint32_t ad = sb + (aRow + mt * 16) * TSTRIDE + aCol + kOff;
                ldsm_x4(ah[mt][0], ah[mt][1], ah[mt][2], ah[mt][3], ad);
            }
            #pragma unroll
            for (int np = 0; np < 2; np++) {
                uint32_t bd = sb + TILE_B + (bRow + np * 16) * TSTRIDE + bCol + kOff;
                ldsm_x4(bh[np*2][0], bh[np*2][1], bh[np*2+1][0], bh[np*2+1][1], bd);
            }
            #pragma unroll
            for (int mt = 0; mt < 4; mt++)
                #pragma unroll
                for (int nt = 0; nt < 4; nt++)
                    mma16816(acc[mt][nt], ah[mt], bh[nt]);
        }
    }

    int g = lane >> 2, tg = lane & 3;
    #pragma unroll
    for (int mt = 0; mt < 4; mt++) {
        int r0 = bm + wm * 64 + mt * 16 + g;
        #pragma unroll
        for (int nt = 0; nt < 4; nt++) {
            int col = bn + wn * 32 + nt * 8 + tg * 2;
            float b0 = bias[col], b1 = bias[col + 1];
            size_t o0 = (size_t)r0 * Nn + col;
            size_t o1 = (size_t)(r0 + 8) * Nn + col;
            float v00 = acc[mt][nt][0] + b0, v01 = acc[mt][nt][1] + b1;
            float v10 = acc[mt][nt][2] + b0, v11 = acc[mt][nt][3] + b1;
            if (MODE == 2) {
                *(uint32_t*)&Cb[o0] = pack_bf16x2(v00, v01);
                *(uint32_t*)&Cb[o1] = pack_bf16x2(v10, v11);
            } else {
                float2 r00 = *(const float2*)&R[o0];
                float2 r11 = *(const float2*)&R[o1];
                *(float2*)&Cf[o0] = make_float2(v00 + r00.x, v01 + r00.y);
                *(float2*)&Cf[o1] = make_float2(v10 + r11.x, v11 + r11.y);
            }
        }
    }
}

// merged q/k/v projection GEMM (768 tiles) + emb reduce (16 tiles)
__global__ void __launch_bounds__(256) qkv_gemm_kernel(
    const float* __restrict__ bq, const float* __restrict__ bk, const float* __restrict__ bv,
    const float* __restrict__ bemb) {
    extern __shared__ char smem[];
    uint32_t sbase = smem_u32(smem);
    int tile = blockIdx.x;
    if (tile >= 768) {
        int base = (tile - 768) * 1024;
        for (int j4 = 0; j4 < 4; j4++) {
            int idx = base + threadIdx.x + j4 * 256;
            int bb = idx >> 11, j = idx & 2047;
            float s = bemb[j];
            #pragma unroll
            for (int ky = 0; ky < 8; ky++) s += g_embp[(ky * 8 + bb) * 2048 + j];
            g_embo[bb * 2048 + j] = s;
        }
        return;
    }
    const __nv_bfloat16 *A, *Bw; const float* bias; __nv_bfloat16* Cb; int K;
    int bm, bn;
    if (tile < 512) {            // Q: 64 x 8 tiles
        A = g_xnh; Bw = g_wq; bias = bq; Cb = g_qh; K = 1024;
        bm = (tile >> 3) * 128; bn = (tile & 7) * 128;
    } else if (tile < 640) {     // K
        tile -= 512;
        A = g_xfh; Bw = g_wk; bias = bk; Cb = g_kh; K = 768;
        bm = (tile >> 3) * 128; bn = (tile & 7) * 128;
    } else {                     // V
        tile -= 640;
        A = g_xfh; Bw = g_wv; bias = bv; Cb = g_vh; K = 768;
        bm = (tile >> 3) * 128; bn = (tile & 7) * 128;
    }
    gemm_body<2>(A, Bw, bias, nullptr, nullptr, Cb, bm, bn, 1024, K, sbase);
}

// out-projection GEMM + residual
__global__ void __launch_bounds__(256) outproj_gemm_kernel(
    const float* __restrict__ bout, const float* __restrict__ x, float* __restrict__ out) {
    extern __shared__ char smem[];
    uint32_t sbase = smem_u32(smem);
    gemm_body<1>(g_hnh, g_wo, bout, x, out, nullptr, blockIdx.y * 128, blockIdx.x * 128,
                 1024, 1024, sbase);
}

// ================= FA2-style attention: 256 q-rows/CTA (two 128-row passes over staged K/V) =================
__global__ void __launch_bounds__(256) attn_mma_kernel() {
    extern __shared__ char smem[];
    __nv_bfloat16* Ks = (__nv_bfloat16*)smem;          // 256 x 72
    __nv_bfloat16* Vs = Ks + 256 * 72;
    uint32_t sbK = smem_u32(Ks), sbV = smem_u32(Vs);

    int tid = threadIdx.x, w = tid >> 5, lane = tid & 31;
    int b = blockIdx.z, h = blockIdx.y;
    int g = lane >> 2, t4 = lane & 3;
    const float SC = 0.125f * 1.44269504f;   // log2-domain scores

    for (int i = tid; i < 2048; i += 256) {
        int r = i >> 3, q8 = i & 7;
        size_t go = (size_t)(b * 256 + r) * 1024 + h * 64 + q8 * 8;
        *(uint4*)(Ks + r * 72 + q8 * 8) = *(const uint4*)(g_kh + go);
        *(uint4*)(Vs + r * 72 + q8 * 8) = *(const uint4*)(g_vh + go);
    }
    __syncthreads();

    uint32_t bRowOff = ((lane >> 4) * 8 + (lane & 7));
    uint32_t bColOff = ((lane >> 3) & 1) * 16;
    uint32_t vRowOff = (((lane >> 3) & 1) * 8 + (lane & 7));
    uint32_t vColOff = (lane >> 4) * 16;

    for (int pass = 0; pass < 2; pass++) {
        int q0 = blockIdx.x * 256 + pass * 128;

        uint32_t aq[4][4];
        const __nv_bfloat16* qb = g_qh + (size_t)(b * 1024 + q0 + w * 16) * 1024 + h * 64;
        #pragma unroll
        for (int ks = 0; ks < 4; ks++) {
            aq[ks][0] = *(const uint32_t*)(qb + (size_t)g * 1024       + ks * 16 + 2 * t4);
            aq[ks][1] = *(const uint32_t*)(qb + (size_t)(g + 8) * 1024 + ks * 16 + 2 * t4);
            aq[ks][2] = *(const uint32_t*)(qb + (size_t)g * 1024       + ks * 16 + 8 + 2 * t4);
            aq[ks][3] = *(const uint32_t*)(qb + (size_t)(g + 8) * 1024 + ks * 16 + 8 + 2 * t4);
        }

        float o[8][4] = {};
        float m0 = -1e30f, m1 = -1e30f, l0 = 0.f, l1 = 0.f;

        for (int c = 0; c < 4; c++) {
            int n0 = c * 64;
            float s[8][4] = {};
            #pragma unroll
            for (int ks = 0; ks < 4; ks++) {
                #pragma unroll
                for (int np = 0; np < 4; np++) {
                    uint32_t r0, r1, r2, r3;
                    uint32_t bd = sbK + (n0 + np * 16 + bRowOff) * 144 + bColOff + ks * 32;
                    ldsm_x4(r0, r1, r2, r3, bd);
                    uint32_t blo[2] = {r0, r1}, bhi[2] = {r2, r3};
                    mma16816(s[np * 2],     aq[ks], blo);
                    mma16816(s[np * 2 + 1], aq[ks], bhi);
                }
            }
            float mx0 = -1e30f, mx1 = -1e30f;
            #pragma unroll
            for (int j = 0; j < 8; j++) {
                #pragma unroll
                for (int r = 0; r < 4; r++) s[j][r] *= SC;
                mx0 = fmaxf(mx0, fmaxf(s[j][0], s[j][1]));
                mx1 = fmaxf(mx1, fmaxf(s[j][2], s[j][3]));
            }
            mx0 = fmaxf(mx0, __shfl_xor_sync(0xffffffffu, mx0, 1));
            mx0 = fmaxf(mx0, __shfl_xor_sync(0xffffffffu, mx0, 2));
            mx1 = fmaxf(mx1, __shfl_xor_sync(0xffffffffu, mx1, 1));
            mx1 = fmaxf(mx1, __shfl_xor_sync(0xffffffffu, mx1, 2));
            float nm0 = fmaxf(m0, mx0), nm1 = fmaxf(m1, mx1);
            float al0 = exp2f(m0 - nm0), al1 = exp2f(m1 - nm1);
            m0 = nm0; m1 = nm1;
            float sum0 = 0.f, sum1 = 0.f;
            #pragma unroll
            for (int j = 0; j < 8; j++) {
                s[j][0] = exp2f(s[j][0] - m0);
                s[j][1] = exp2f(s[j][1] - m0);
                s[j][2] = exp2f(s[j][2] - m1);
                s[j][3] = exp2f(s[j][3] - m1);
                sum0 += s[j][0] + s[j][1];
                sum1 += s[j][2] + s[j][3];
            }
            sum0 += __shfl_xor_sync(0xffffffffu, sum0, 1);
            sum0 += __shfl_xor_sync(0xffffffffu, sum0, 2);
            sum1 += __shfl_xor_sync(0xffffffffu, sum1, 1);
            sum1 += __shfl_xor_sync(0xffffffffu, sum1, 2);
            l0 = l0 * al0 + sum0;
            l1 = l1 * al1 + sum1;
            #pragma unroll
            for (int dt = 0; dt < 8; dt++) {
                o[dt][0] *= al0; o[dt][1] *= al0;
                o[dt][2] *= al1; o[dt][3] *= al1;
            }
            uint32_t pa[4][4];
            #pragma unroll
            for (int j = 0; j < 4; j++) {
                pa[j][0] = pack_bf16x2(s[2*j][0],   s[2*j][1]);
                pa[j][1] = pack_bf16x2(s[2*j][2],   s[2*j][3]);
                pa[j][2] = pack_bf16x2(s[2*j+1][0], s[2*j+1][1]);
                pa[j][3] = pack_bf16x2(s[2*j+1][2], s[2*j+1][3]);
            }
            #pragma unroll
            for (int j = 0; j < 4; j++) {
                #pragma unroll
                for (int dp = 0; dp < 4; dp++) {
                    uint32_t r0, r1, r2, r3;
                    uint32_t vd = sbV + (n0 + j * 16 + vRowOff) * 144 + dp * 32 + vColOff;
                    ldsm_x4_t(r0, r1, r2, r3, vd);
                    uint32_t blo[2] = {r0, r1}, bhi[2] = {r2, r3};
                    mma16816(o[dp * 2],     pa[j], blo);
                    mma16816(o[dp * 2 + 1], pa[j], bhi);
                }
            }
        }
        float inv0 = 1.f / l0, inv1 = 1.f / l1;
        __nv_bfloat16* yb = g_yh + (size_t)(b * 1024 + q0 + w * 16) * 1024 + h * 64;
        #pragma unroll
        for (int dt = 0; dt < 8; dt++) {
            int col = dt * 8 + 2 * t4;
            *(uint32_t*)(yb + (size_t)g * 1024 + col)       = pack_bf16x2(o[dt][0] * inv0, o[dt][1] * inv0);
            *(uint32_t*)(yb + (size_t)(g + 8) * 1024 + col) = pack_bf16x2(o[dt][2] * inv1, o[dt][3] * inv1);
        }
    }
}

// ================= LN(y)*(1+scale)+shift -> silu -> bf16 (vectorized) =================
__global__ void __launch_bounds__(256) modulate_kernel(const float* __restrict__ gam,
                                                       const float* __restrict__ bet) {
    int row = blockIdx.x;
    int b = row >> 10;
    const __nv_bfloat16* yr = g_yh + (size_t)row * 1024;
    int i0 = threadIdx.x * 4;
    uint2 y2 = *(const uint2*)(yr + i0);
    __nv_bfloat162 p0 = *(__nv_bfloat162*)&y2.x;
    __nv_bfloat162 p1 = *(__nv_bfloat162*)&y2.y;
    float v0 = __bfloat162float(p0.x), v1 = __bfloat162float(p0.y);
    float v2 = __bfloat162float(p1.x), v3 = __bfloat162float(p1.y);
    float sum = v0 + v1 + v2 + v3;
    float sq  = v0 * v0 + v1 * v1 + v2 * v2 + v3 * v3;
    __shared__ float s1[8], s2[8];
    #pragma unroll
    for (int o = 16; o; o >>= 1) {
        sum += __shfl_xor_sync(0xffffffffu, sum, o);
        sq  += __shfl_xor_sync(0xffffffffu, sq,  o);
    }
    int w = threadIdx.x >> 5, l = threadIdx.x & 31;
    if (l == 0) { s1[w] = sum; s2[w] = sq; }
    __syncthreads();
    __shared__ float mean_s, inv_s;
    if (threadIdx.x == 0) {
        float ts = 0.f, tq = 0.f;
        for (int i = 0; i < 8; i++) { ts += s1[i]; tq += s2[i]; }
        float mean = ts * (1.f / 1024.f);
        float var = tq * (1.f / 1024.f) - mean * mean;
        mean_s = mean;
        inv_s = rsqrtf(var + 1e-5f);
    }
    __syncthreads();
    float mean = mean_s, inv = inv_s;
    float4 gg = *(const float4*)(gam + i0);
    float4 bb = *(const float4*)(bet + i0);
    float4 sc = *(const float4*)(g_embo + b * 2048 + i0);
    float4 shf = *(const float4*)(g_embo + b * 2048 + 1024 + i0);
    float n0 = (v0 - mean) * inv * gg.x + bb.x;
    float n1 = (v1 - mean) * inv * gg.y + bb.y;
    float n2 = (v2 - mean) * inv * gg.z + bb.z;
    float n3 = (v3 - mean) * inv * gg.w + bb.w;
    float h0 = n0 * (1.f + sc.x) + shf.x;
    float h1 = n1 * (1.f + sc.y) + shf.y;
    float h2 = n2 * (1.f + sc.z) + shf.z;
    float h3 = n3 * (1.f + sc.w) + shf.w;
    h0 = h0 / (1.f + __expf(-h0));
    h1 = h1 / (1.f + __expf(-h1));
    h2 = h2 / (1.f + __expf(-h2));
    h3 = h3 / (1.f + __expf(-h3));
    uint2 o2;
    o2.x = pack_bf16x2(h0, h1);
    o2.y = pack_bf16x2(h2, h3);
    *(uint2*)(g_hnh + (size_t)row * 1024 + i0) = o2;
}

// ================= launch =================
extern "C" void kernel_launch(void* const* d_in, const int* in_sizes, int n_in,
                              void* d_out, int out_size) {
    const float* x     = (const float*)d_in[0];
    const float* xf    = (const float*)d_in[1];
    const float* emb   = (const float*)d_in[2];
    const float* ln_g  = (const float*)d_in[3];
    const float* ln_b  = (const float*)d_in[4];
    const float* cln_g = (const float*)d_in[5];
    const float* cln_b = (const float*)d_in[6];
    const float* Wq    = (const float*)d_in[7];
    const float* bq    = (const float*)d_in[8];
    const float* Wk    = (const float*)d_in[9];
    const float* bk    = (const float*)d_in[10];
    const float* Wv    = (const float*)d_in[11];
    const float* bv    = (const float*)d_in[12];
    const float* sln_g = (const float*)d_in[13];
    const float* sln_b = (const float*)d_in[14];
    const float* Wemb  = (const float*)d_in[15];
    const float* bemb  = (const float*)d_in[16];
    const float* Wout  = (const float*)d_in[17];
    const float* bout  = (const float*)d_in[18];
    float* out = (float*)d_out;

    static const int SMEM_ATTN = 2 * 256 * 144;      // 73728
    cudaFuncSetAttribute(qkv_gemm_kernel,     cudaFuncAttributeMaxDynamicSharedMemorySize, GEMM_SMEM);
    cudaFuncSetAttribute(outproj_gemm_kernel, cudaFuncAttributeMaxDynamicSharedMemorySize, GEMM_SMEM);
    cudaFuncSetAttribute(attn_mma_kernel,     cudaFuncAttributeMaxDynamicSharedMemorySize, SMEM_ATTN);

    // 1) preprocess: LN(x), LN(xf), weight transposes, emb split-K partials
    preprocess_kernel<<<13888, 256>>>(x, ln_g, ln_b, xf, cln_g, cln_b,
                                      Wq, Wk, Wv, Wout, emb, Wemb);

    // 2) q/k/v projections + emb reduce
    qkv_gemm_kernel<<<784, 256, GEMM_SMEM>>>(bq, bk, bv, bemb);

    // 3) attention (256 q-rows per CTA)
    attn_mma_kernel<<<dim3(4, 16, 8), 256, SMEM_ATTN>>>();

    // 4) modulate
    modulate_kernel<<<8192, 256>>>(sln_g, sln_b);

    // 5) output projection + residual
    outproj_gemm_kernel<<<dim3(8, 64), 256, GEMM_SMEM>>>(bout, x, out);
}